// round 10
// baseline (speedup 1.0000x reference)
#include <cuda_runtime.h>
#include <cuda_bf16.h>
#include <math_constants.h>
#include <math.h>
#include <cstdint>

// B=4, L=1024, D=1024, H=16, HD=64.
// S[q,k] = (q+rr)·x_k + (q+rw)·pos[k-q+L] == Â[q]·K̂[k], K=128 (angle addition).
// R10: flash at 64q/4warps/32k-tiles -> 100KB smem -> 2 CTAs/SM; vt smem transpose.

// ---------------------------------------------------------------------------
// Device scratch
// ---------------------------------------------------------------------------
__device__ __align__(16) __nv_bfloat16 g_xh[4096 * 1024];
__device__ __align__(16) __nv_bfloat16 g_xl[4096 * 1024];
__device__ __align__(16) __nv_bfloat16 g_wh[2048 * 1024];      // Wqv^T hi [n][k]
__device__ __align__(16) __nv_bfloat16 g_wl[2048 * 1024];
__device__ __align__(16) float g_u[4096 * 1024];               // q + rr
__device__ __align__(16) float g_v[4096 * 1024];               // v fp32
__device__ __align__(16) __nv_bfloat16 g_vth[64 * 64 * 1024];  // V^T hi [bh*64+d][tok]
__device__ __align__(16) __nv_bfloat16 g_vtl[64 * 64 * 1024];  // V^T lo
__device__ __align__(16) float g_trig[1024 * 64];              // [p][i]=sin, [p][32+i]=cos
__device__ __align__(16) __nv_bfloat16 g_Ah[(size_t)64 * 1024 * 128];
__device__ __align__(16) __nv_bfloat16 g_Al[(size_t)64 * 1024 * 128];
__device__ __align__(16) __nv_bfloat16 g_Kh[(size_t)64 * 1024 * 128];
__device__ __align__(16) __nv_bfloat16 g_Kl[(size_t)64 * 1024 * 128];

// ---------------------------------------------------------------------------
// helpers
// ---------------------------------------------------------------------------
__device__ __forceinline__ uint32_t smem_u32(const void* p) {
    uint32_t a;
    asm("{ .reg .u64 t; cvta.to.shared.u64 t, %1; cvt.u32.u64 %0, t; }" : "=r"(a) : "l"(p));
    return a;
}
__device__ __forceinline__ void mma_bf16(float* c, const uint32_t* a, const uint32_t* b) {
    asm volatile(
        "mma.sync.aligned.m16n8k16.row.col.f32.bf16.bf16.f32 "
        "{%0,%1,%2,%3}, {%4,%5,%6,%7}, {%8,%9}, {%0,%1,%2,%3};"
        : "+f"(c[0]), "+f"(c[1]), "+f"(c[2]), "+f"(c[3])
        : "r"(a[0]), "r"(a[1]), "r"(a[2]), "r"(a[3]), "r"(b[0]), "r"(b[1]));
}
__device__ __forceinline__ void ldsm4(uint32_t* r, uint32_t addr) {
    asm volatile("ldmatrix.sync.aligned.m8n8.x4.shared.b16 {%0,%1,%2,%3}, [%4];"
        : "=r"(r[0]), "=r"(r[1]), "=r"(r[2]), "=r"(r[3]) : "r"(addr));
}
__device__ __forceinline__ uint32_t pack2(float e0, float e1) {
    __nv_bfloat162 h;
    h.x = __float2bfloat16(e0);
    h.y = __float2bfloat16(e1);
    return *(uint32_t*)&h;
}
#define CP16(saddr, gptr) \
    asm volatile("cp.async.ca.shared.global [%0], [%1], 16;" \
        :: "r"(saddr), "l"(__cvta_generic_to_global(gptr)))
#define CP_COMMIT() asm volatile("cp.async.commit_group;")
#define CP_WAIT(n)  asm volatile("cp.async.wait_group %0;" :: "n"(n))

// ---------------------------------------------------------------------------
// K0: trig table. K1: hi/lo decomposition of x and Wqv^T.
// ---------------------------------------------------------------------------
__global__ void k_trig() {
    int p = blockIdx.x, i = threadIdx.x;
    double f = exp(-(double)i * (log(10000.0) / 31.0));
    double ang = (double)p * f;
    g_trig[p * 64 + i] = (float)sin(ang);
    g_trig[p * 64 + 32 + i] = (float)cos(ang);
}
__global__ __launch_bounds__(256) void k_decomp_x(const float* __restrict__ x) {
    int idx = blockIdx.x * 256 + threadIdx.x;
    float f = x[idx];
    __nv_bfloat16 h = __float2bfloat16(f);
    g_xh[idx] = h;
    g_xl[idx] = __float2bfloat16(f - __bfloat162float(h));
}
__global__ __launch_bounds__(256) void k_decomp_w(const float* __restrict__ W) {
    int idx = blockIdx.x * 256 + threadIdx.x;
    int k = idx >> 11, n = idx & 2047;
    float f = W[idx];
    __nv_bfloat16 h = __float2bfloat16(f);
    g_wh[n * 1024 + k] = h;
    g_wl[n * 1024 + k] = __float2bfloat16(f - __bfloat162float(h));
}

// ---------------------------------------------------------------------------
// K2: qv = x @ Wqv. smem-staged cp.async + ldmatrix (validated R7).
// ---------------------------------------------------------------------------
#define STAGE_BYTES 30720
#define QV_SMEM (2 * STAGE_BYTES)

__device__ __forceinline__ void stage_load(
    uint32_t sb, const __nv_bfloat16* Ah, const __nv_bfloat16* Al,
    const __nv_bfloat16* Bh, const __nv_bfloat16* Bl,
    size_t aRow, size_t bRow, int lda, int k0, int tid)
{
#pragma unroll
    for (int it = 0; it < 2; it++) {
        int idx = tid + it * 256;
        int r = idx >> 2, c = idx & 3;
        uint32_t so = r * 80 + c * 16;
        size_t go = (aRow + r) * (size_t)lda + k0 + c * 8;
        CP16(sb + so, Ah + go);
        CP16(sb + 10240 + so, Al + go);
    }
    {
        int r = tid >> 2, c = tid & 3;
        uint32_t so = r * 80 + c * 16;
        size_t go = (bRow + r) * (size_t)lda + k0 + c * 8;
        CP16(sb + 20480 + so, Bh + go);
        CP16(sb + 25600 + so, Bl + go);
    }
}
__device__ __forceinline__ void stage_mma(uint32_t sb, int wm, int wn, int lane,
                                          float acc[2][4][4])
{
    int rsel = lane & 15;
    uint32_t csel = ((lane >> 4) << 3);
#pragma unroll
    for (int kc = 0; kc < 32; kc += 16) {
        uint32_t colB = (kc + csel) * 2;
        uint32_t ah[2][4], al[2][4], bhf[2][4], blf[2][4];
#pragma unroll
        for (int mi = 0; mi < 2; mi++) {
            uint32_t ad = sb + (uint32_t)((wm + mi * 16 + rsel) * 80) + colB;
            ldsm4(ah[mi], ad);
            ldsm4(al[mi], ad + 10240);
        }
#pragma unroll
        for (int p = 0; p < 2; p++) {
            uint32_t bd = sb + 20480 + (uint32_t)((wn + p * 16 + rsel) * 80) + colB;
            ldsm4(bhf[p], bd);
            ldsm4(blf[p], bd + 5120);
        }
#pragma unroll
        for (int mi = 0; mi < 2; mi++)
#pragma unroll
            for (int ni = 0; ni < 4; ni++) {
                int p = ni >> 1, o = ni & 1;
                uint32_t bq[2]  = { bhf[p][o], bhf[p][o + 2] };
                uint32_t bql[2] = { blf[p][o], blf[p][o + 2] };
                mma_bf16(acc[mi][ni], ah[mi], bq);
                mma_bf16(acc[mi][ni], ah[mi], bql);
                mma_bf16(acc[mi][ni], al[mi], bq);
            }
    }
}

__global__ __launch_bounds__(256, 2) void k_qv_mma(const float* __restrict__ rr) {
    extern __shared__ char dynsmem[];
    uint32_t sbase = smem_u32(dynsmem);
    int tid = threadIdx.x, wid = tid >> 5, lane = tid & 31;
    int wm = (wid >> 1) * 32, wn = (wid & 1) * 32;
    int g = lane >> 2, t = lane & 3;
    int brow = blockIdx.y * 128, bcol = blockIdx.x * 64;

    float acc[2][4][4] = {};
    const int NS = 32;
    stage_load(sbase, g_xh, g_xl, g_wh, g_wl, brow, bcol, 1024, 0, tid);
    CP_COMMIT();
    for (int s = 0; s < NS; s++) {
        if (s + 1 < NS) {
            stage_load(sbase + ((s + 1) & 1) * STAGE_BYTES, g_xh, g_xl, g_wh, g_wl,
                       brow, bcol, 1024, (s + 1) * 32, tid);
            CP_COMMIT();
            CP_WAIT(1);
        } else {
            CP_WAIT(0);
        }
        __syncthreads();
        stage_mma(sbase + (s & 1) * STAGE_BYTES, wm, wn, lane, acc);
        __syncthreads();
    }

    bool is_q = (bcol < 1024);
#pragma unroll
    for (int mi = 0; mi < 2; mi++)
#pragma unroll
        for (int ni = 0; ni < 4; ni++) {
            int row0 = brow + wm + mi * 16 + g;
            int cn = bcol + wn + ni * 8 + 2 * t;
            float2 v0 = make_float2(acc[mi][ni][0], acc[mi][ni][1]);
            float2 v1 = make_float2(acc[mi][ni][2], acc[mi][ni][3]);
            if (is_q) {
                float2 rb = *(const float2*)(rr + cn);
                v0.x += rb.x; v0.y += rb.y;
                v1.x += rb.x; v1.y += rb.y;
                *(float2*)&g_u[(size_t)row0 * 1024 + cn] = v0;
                *(float2*)&g_u[(size_t)(row0 + 8) * 1024 + cn] = v1;
            } else {
                *(float2*)&g_v[(size_t)row0 * 1024 + cn - 1024] = v0;
                *(float2*)&g_v[(size_t)(row0 + 8) * 1024 + cn - 1024] = v1;
            }
        }
}

// ---------------------------------------------------------------------------
// K3: V^T bf16 hi/lo via smem tile transpose (both sides coalesced).
// Grid: (16 tok-tiles, 64 bh), 256 threads.
// ---------------------------------------------------------------------------
__global__ __launch_bounds__(256) void k_vt() {
    __shared__ float tile[64][65];
    int bh = blockIdx.y, tok0 = blockIdx.x * 64;
    int b = bh >> 4, h = bh & 15;
    int tid = threadIdx.x;
#pragma unroll
    for (int it = 0; it < 16; it++) {
        int idx = tid + it * 256;          // 0..4095
        int r = idx >> 6, c = idx & 63;    // r = tok, c = d
        tile[r][c] = g_v[(size_t)(b * 1024 + tok0 + r) * 1024 + h * 64 + c];
    }
    __syncthreads();
#pragma unroll
    for (int it = 0; it < 16; it++) {
        int idx = tid + it * 256;
        int r = idx >> 6, c = idx & 63;    // r = d, c = tok
        float f = tile[c][r];
        __nv_bfloat16 hi = __float2bfloat16(f);
        size_t o = (size_t)(bh * 64 + r) * 1024 + tok0 + c;
        g_vth[o] = hi;
        g_vtl[o] = __float2bfloat16(f - __bfloat162float(hi));
    }
}

// ---------------------------------------------------------------------------
// K4a/K4b: build Â and K̂ rows (hi/lo bf16, 128-wide).
// ---------------------------------------------------------------------------
__global__ __launch_bounds__(256) void k_build_A(const float* __restrict__ rr,
                                                 const float* __restrict__ rw) {
    int idx = blockIdx.x * 256 + threadIdx.x;
    int bh = idx >> 10, q = idx & 1023;
    int b = bh >> 4, h = bh & 15;
    const float* up = g_u + (size_t)(b * 1024 + q) * 1024 + h * 64;
    __nv_bfloat16* ah = g_Ah + (size_t)idx * 128;
    __nv_bfloat16* al = g_Al + (size_t)idx * 128;
    const float* tg = g_trig + q * 64;
#pragma unroll 8
    for (int i = 0; i < 32; i++) {
        float u0 = up[i], u1 = up[32 + i];
        __nv_bfloat16 h0 = __float2bfloat16(u0);
        ah[i] = h0; al[i] = __float2bfloat16(u0 - __bfloat162float(h0));
        __nv_bfloat16 h1 = __float2bfloat16(u1);
        ah[32 + i] = h1; al[32 + i] = __float2bfloat16(u1 - __bfloat162float(h1));
        float w0 = u0 - rr[h * 64 + i] + rw[h * 64 + i];
        float w1 = u1 - rr[h * 64 + 32 + i] + rw[h * 64 + 32 + i];
        float sq = tg[i], cq = tg[32 + i];
        float a1 = w0 * cq + w1 * sq;
        float a2 = w1 * cq - w0 * sq;
        __nv_bfloat16 hh1 = __float2bfloat16(a1);
        ah[64 + i] = hh1; al[64 + i] = __float2bfloat16(a1 - __bfloat162float(hh1));
        __nv_bfloat16 hh2 = __float2bfloat16(a2);
        ah[96 + i] = hh2; al[96 + i] = __float2bfloat16(a2 - __bfloat162float(hh2));
    }
}
__global__ __launch_bounds__(256) void k_build_K(const float* __restrict__ x) {
    int idx = blockIdx.x * 256 + threadIdx.x;
    int bh = idx >> 10, k = idx & 1023;
    int b = bh >> 4, h = bh & 15;
    const float* xp = x + (size_t)(b * 1024 + k) * 1024 + h * 64;
    __nv_bfloat16* kh = g_Kh + (size_t)idx * 128;
    __nv_bfloat16* kl = g_Kl + (size_t)idx * 128;
    const float* tg = g_trig + k * 64;
#pragma unroll 8
    for (int i = 0; i < 32; i++) {
        float x0 = xp[i], x1 = xp[32 + i];
        __nv_bfloat16 h0 = __float2bfloat16(x0);
        kh[i] = h0; kl[i] = __float2bfloat16(x0 - __bfloat162float(h0));
        __nv_bfloat16 h1 = __float2bfloat16(x1);
        kh[32 + i] = h1; kl[32 + i] = __float2bfloat16(x1 - __bfloat162float(h1));
        float s = tg[i], c = tg[32 + i];
        __nv_bfloat16 h2 = __float2bfloat16(s);
        kh[64 + i] = h2; kl[64 + i] = __float2bfloat16(s - __bfloat162float(h2));
        __nv_bfloat16 h3 = __float2bfloat16(c);
        kh[96 + i] = h3; kl[96 + i] = __float2bfloat16(c - __bfloat162float(h3));
    }
}

// ---------------------------------------------------------------------------
// K5: flash attention, 2 CTAs/SM. Block = 64 q rows, 4 warps of 16q; k-tiles
// of 32, double-buffered K̂+V; online softmax; all operands via ldmatrix.
//
// smem (80B rows, 32-col chunks — validated layout):
//   Â  hi chunk c @ c*5120 (64 rows); lo +20480.            [0, 40960)
//   stage s @ 40960 + s*30720:
//     K̂ hi chunk c @ +c*2560 (32 rows); lo +10240.          (20480 B)
//     V  hi @ +20480 (64 d-rows x 32 tok = 5120); lo +5120. (10240 B)
// ---------------------------------------------------------------------------
#define FB_ACH 5120
#define FB_ALO 20480
#define FB_KBASE 40960
#define FB_KCH 2560
#define FB_KLO 10240
#define FB_VOFF 20480
#define FB_VLO 5120
#define FB_STAGE 30720
#define FB_SMEM (FB_KBASE + 2 * FB_STAGE)   // 102400

__device__ __forceinline__ void fb_load_kv(uint32_t sb, int bh, size_t kRow,
                                           int kb, int buf, int tid) {
    uint32_t st = sb + FB_KBASE + buf * FB_STAGE;
#pragma unroll
    for (int it = 0; it < 4; it++) {
        int idx = tid + it * 128;              // 0..511
        int r = idx >> 4, cc = idx & 15;       // r: k-row 0..31
        uint32_t so = (cc >> 2) * FB_KCH + r * 80 + (cc & 3) * 16;
        size_t go = (kRow + kb + r) * 128 + cc * 8;
        CP16(st + so, g_Kh + go);
        CP16(st + FB_KLO + so, g_Kl + go);
    }
    uint32_t stV = st + FB_VOFF;
#pragma unroll
    for (int it = 0; it < 2; it++) {
        int idx = tid + it * 128;              // 0..255
        int r = idx >> 2, c4 = idx & 3;        // r: d-row 0..63
        uint32_t so = r * 80 + c4 * 16;
        size_t go = (size_t)(bh * 64 + r) * 1024 + kb + c4 * 8;
        CP16(stV + so, g_vth + go);
        CP16(stV + FB_VLO + so, g_vtl + go);
    }
}

__global__ __launch_bounds__(128, 2) void k_flash(const int* __restrict__ mask,
                                                  float* __restrict__ out) {
    extern __shared__ char dynsmem[];
    __shared__ int msk[1024];
    uint32_t sb = smem_u32(dynsmem);
    int bh = blockIdx.y, b = bh >> 4, h = bh & 15;
    int brow = blockIdx.x * 64;
    int tid = threadIdx.x, wid = tid >> 5, lane = tid & 31;
    int wm = wid * 16;
    int g = lane >> 2, t = lane & 3;
    int rsel = lane & 15;
    uint32_t csel = ((lane >> 4) << 3);

    size_t aRow = (size_t)bh * 1024 + brow;
    size_t kRow = (size_t)bh * 1024;

    // ---- load Â (once): 64 rows x 128 halves, hi+lo ----
#pragma unroll
    for (int it = 0; it < 8; it++) {
        int idx = tid + it * 128;              // 0..1023
        int r = idx >> 4, cc = idx & 15;
        uint32_t so = (cc >> 2) * FB_ACH + r * 80 + (cc & 3) * 16;
        size_t go = (aRow + r) * 128 + cc * 8;
        CP16(sb + so, g_Ah + go);
        CP16(sb + FB_ALO + so, g_Al + go);
    }
    fb_load_kv(sb, bh, kRow, 0, 0, tid);
    CP_COMMIT();
    for (int i = tid; i < 1024; i += 128) msk[i] = mask[b * 1024 + i];

    float oacc[8][4] = {};
    float m0 = -CUDART_INF_F, m1 = -CUDART_INF_F, l0 = 0.0f, l1 = 0.0f;

    const int NT = 32;
    for (int kt = 0; kt < NT; kt++) {
        if (kt + 1 < NT) {
            fb_load_kv(sb, bh, kRow, (kt + 1) * 32, (kt + 1) & 1, tid);
            CP_COMMIT();
            CP_WAIT(1);
        } else {
            CP_WAIT(0);
        }
        __syncthreads();

        // ---- S tile: 16q x 32k per warp, K=128 ----
        uint32_t Ks = sb + FB_KBASE + (kt & 1) * FB_STAGE;
        float sacc[4][4] = {};
#pragma unroll
        for (int ks = 0; ks < 8; ks++) {
            int c = ks >> 1;
            uint32_t colB = (((ks & 1) * 16) + csel) * 2;
            uint32_t ah[4], al[4], bhf[2][4], blf[2][4];
            uint32_t ad = sb + (uint32_t)(c * FB_ACH) + (uint32_t)((wm + rsel) * 80) + colB;
            ldsm4(ah, ad);
            ldsm4(al, ad + FB_ALO);
#pragma unroll
            for (int p = 0; p < 2; p++) {
                uint32_t kd = Ks + (uint32_t)(c * FB_KCH) + (uint32_t)((p * 16 + rsel) * 80) + colB;
                ldsm4(bhf[p], kd);
                ldsm4(blf[p], kd + FB_KLO);
            }
#pragma unroll
            for (int ni = 0; ni < 4; ni++) {
                int p = ni >> 1, o = ni & 1;
                uint32_t bq[2]  = { bhf[p][o], bhf[p][o + 2] };
                uint32_t bql[2] = { blf[p][o], blf[p][o + 2] };
                mma_bf16(sacc[ni], ah, bq);
                mma_bf16(sacc[ni], ah, bql);
                mma_bf16(sacc[ni], al, bq);
            }
        }

        // ---- online softmax ----
        int kb = kt * 32;
        float tmax0 = -CUDART_INF_F, tmax1 = -CUDART_INF_F;
#pragma unroll
        for (int ni = 0; ni < 4; ni++) {
            int kc = kb + ni * 8 + 2 * t;
            if (msk[kc] == 0)     { sacc[ni][0] = -CUDART_INF_F; sacc[ni][2] = -CUDART_INF_F; }
            if (msk[kc + 1] == 0) { sacc[ni][1] = -CUDART_INF_F; sacc[ni][3] = -CUDART_INF_F; }
            tmax0 = fmaxf(tmax0, fmaxf(sacc[ni][0], sacc[ni][1]));
            tmax1 = fmaxf(tmax1, fmaxf(sacc[ni][2], sacc[ni][3]));
        }
        tmax0 = fmaxf(tmax0, __shfl_xor_sync(0xffffffffu, tmax0, 1));
        tmax0 = fmaxf(tmax0, __shfl_xor_sync(0xffffffffu, tmax0, 2));
        tmax1 = fmaxf(tmax1, __shfl_xor_sync(0xffffffffu, tmax1, 1));
        tmax1 = fmaxf(tmax1, __shfl_xor_sync(0xffffffffu, tmax1, 2));
        float nm0 = fmaxf(m0, tmax0), nm1 = fmaxf(m1, tmax1);
        float sc0 = __expf(m0 - nm0), sc1 = __expf(m1 - nm1);
        m0 = nm0; m1 = nm1;

        float rs0 = 0.0f, rs1 = 0.0f;
        uint32_t aPh[2][4], aPl[2][4];
#pragma unroll
        for (int ni = 0; ni < 4; ni++) {
            float p0 = __expf(sacc[ni][0] - nm0);
            float p1 = __expf(sacc[ni][1] - nm0);
            float p2 = __expf(sacc[ni][2] - nm1);
            float p3 = __expf(sacc[ni][3] - nm1);
            rs0 += p0 + p1;
            rs1 += p2 + p3;
            int c2 = ni >> 1, o = ni & 1;
            __nv_bfloat162 hp;
            hp.x = __float2bfloat16(p0); hp.y = __float2bfloat16(p1);
            aPh[c2][o * 2 + 0] = *(uint32_t*)&hp;
            aPl[c2][o * 2 + 0] = pack2(p0 - __bfloat162float(hp.x), p1 - __bfloat162float(hp.y));
            hp.x = __float2bfloat16(p2); hp.y = __float2bfloat16(p3);
            aPh[c2][o * 2 + 1] = *(uint32_t*)&hp;
            aPl[c2][o * 2 + 1] = pack2(p2 - __bfloat162float(hp.x), p3 - __bfloat162float(hp.y));
        }
        rs0 += __shfl_xor_sync(0xffffffffu, rs0, 1);
        rs0 += __shfl_xor_sync(0xffffffffu, rs0, 2);
        rs1 += __shfl_xor_sync(0xffffffffu, rs1, 1);
        rs1 += __shfl_xor_sync(0xffffffffu, rs1, 2);
        l0 = l0 * sc0 + rs0;
        l1 = l1 * sc1 + rs1;
#pragma unroll
        for (int ni2 = 0; ni2 < 8; ni2++) {
            oacc[ni2][0] *= sc0; oacc[ni2][1] *= sc0;
            oacc[ni2][2] *= sc1; oacc[ni2][3] *= sc1;
        }

        // ---- PV: O += P @ V from smem V stage ----
        uint32_t Vs = Ks + FB_VOFF;
#pragma unroll
        for (int c2 = 0; c2 < 2; c2++) {
            uint32_t colB = ((c2 * 16) + csel) * 2;
            uint32_t bvh[4][4], bvl[4][4];
#pragma unroll
            for (int p = 0; p < 4; p++) {
                uint32_t vd = Vs + (uint32_t)((p * 16 + rsel) * 80) + colB;
                ldsm4(bvh[p], vd);
                ldsm4(bvl[p], vd + FB_VLO);
            }
#pragma unroll
            for (int ni2 = 0; ni2 < 8; ni2++) {
                int p = ni2 >> 1, o = ni2 & 1;
                uint32_t bq[2]  = { bvh[p][o], bvh[p][o + 2] };
                uint32_t bql[2] = { bvl[p][o], bvl[p][o + 2] };
                mma_bf16(oacc[ni2], aPh[c2], bq);
                mma_bf16(oacc[ni2], aPh[c2], bql);
                mma_bf16(oacc[ni2], aPl[c2], bq);
            }
        }
        __syncthreads();   // release stage (kt&1) before refill in iter kt+1
    }

    // ---- epilogue ----
    float inv0 = 1.0f / l0, inv1 = 1.0f / l1;
    int row0 = b * 1024 + brow + wm + g;
    int row1 = row0 + 8;
#pragma unroll
    for (int ni2 = 0; ni2 < 8; ni2++) {
        int cn = h * 64 + ni2 * 8 + 2 * t;
        *(float2*)&out[(size_t)row0 * 1024 + cn] =
            make_float2(oacc[ni2][0] * inv0, oacc[ni2][1] * inv0);
        *(float2*)&out[(size_t)row1 * 1024 + cn] =
            make_float2(oacc[ni2][2] * inv1, oacc[ni2][3] * inv1);
    }
}

// ---------------------------------------------------------------------------
extern "C" void kernel_launch(void* const* d_in, const int* in_sizes, int n_in,
                              void* d_out, int out_size) {
    (void)in_sizes; (void)n_in; (void)out_size;
    const float* x    = (const float*)d_in[0];
    const float* Wqv  = (const float*)d_in[1];
    const float* rr   = (const float*)d_in[2];
    const float* rw   = (const float*)d_in[3];
    const int*   mask = (const int*)d_in[4];
    float* out = (float*)d_out;

    cudaFuncSetAttribute(k_qv_mma, cudaFuncAttributeMaxDynamicSharedMemorySize, QV_SMEM);
    cudaFuncSetAttribute(k_flash,  cudaFuncAttributeMaxDynamicSharedMemorySize, FB_SMEM);

    k_trig<<<1024, 32>>>();
    k_decomp_x<<<16384, 256>>>(x);
    k_decomp_w<<<8192, 256>>>(Wqv);
    k_qv_mma<<<dim3(32, 32), 256, QV_SMEM>>>(rr);
    k_vt<<<dim3(16, 64), 256>>>();
    k_build_A<<<256, 256>>>(rr, rw);
    k_build_K<<<256, 256>>>(x);
    k_flash<<<dim3(16, 64), 128, FB_SMEM>>>(mask, out);
}

// round 11
// speedup vs baseline: 1.1865x; 1.1865x over previous
#include <cuda_runtime.h>
#include <cuda_fp16.h>
#include <math_constants.h>
#include <math.h>
#include <cstdint>

// B=4, L=1024, D=1024, H=16, HD=64.
// S[q,k] = (q+rr)·x_k + (q+rw)·pos[k-q+L] == Â[q]·K̂[k], K=128 (angle addition).
// R11: all-fp16 splits; qv v-half 2-product; PV 1-product; single-sync pipelines.

// ---------------------------------------------------------------------------
// Device scratch
// ---------------------------------------------------------------------------
__device__ __align__(16) __half g_xh[4096 * 1024];
__device__ __align__(16) __half g_xl[4096 * 1024];
__device__ __align__(16) __half g_wh[2048 * 1024];      // Wqv^T hi [n][k]
__device__ __align__(16) __half g_wl[2048 * 1024];
__device__ __align__(16) float g_u[4096 * 1024];        // q + rr
__device__ __align__(16) float g_v[4096 * 1024];        // v fp32
__device__ __align__(16) __half g_vth[64 * 64 * 1024];  // V^T fp16 [bh*64+d][tok]
__device__ __align__(16) float g_trig[1024 * 64];       // [p][i]=sin, [p][32+i]=cos
__device__ __align__(16) __half g_Ah[(size_t)64 * 1024 * 128];
__device__ __align__(16) __half g_Al[(size_t)64 * 1024 * 128];
__device__ __align__(16) __half g_Kh[(size_t)64 * 1024 * 128];
__device__ __align__(16) __half g_Kl[(size_t)64 * 1024 * 128];

// ---------------------------------------------------------------------------
// helpers
// ---------------------------------------------------------------------------
__device__ __forceinline__ uint32_t smem_u32(const void* p) {
    uint32_t a;
    asm("{ .reg .u64 t; cvta.to.shared.u64 t, %1; cvt.u32.u64 %0, t; }" : "=r"(a) : "l"(p));
    return a;
}
__device__ __forceinline__ void mma_f16(float* c, const uint32_t* a, const uint32_t* b) {
    asm volatile(
        "mma.sync.aligned.m16n8k16.row.col.f32.f16.f16.f32 "
        "{%0,%1,%2,%3}, {%4,%5,%6,%7}, {%8,%9}, {%0,%1,%2,%3};"
        : "+f"(c[0]), "+f"(c[1]), "+f"(c[2]), "+f"(c[3])
        : "r"(a[0]), "r"(a[1]), "r"(a[2]), "r"(a[3]), "r"(b[0]), "r"(b[1]));
}
__device__ __forceinline__ void ldsm4(uint32_t* r, uint32_t addr) {
    asm volatile("ldmatrix.sync.aligned.m8n8.x4.shared.b16 {%0,%1,%2,%3}, [%4];"
        : "=r"(r[0]), "=r"(r[1]), "=r"(r[2]), "=r"(r[3]) : "r"(addr));
}
__device__ __forceinline__ uint32_t packh2(float e0, float e1) {
    __half2 h = __floats2half2_rn(e0, e1);
    return *(uint32_t*)&h;
}
#define CP16(saddr, gptr) \
    asm volatile("cp.async.ca.shared.global [%0], [%1], 16;" \
        :: "r"(saddr), "l"(__cvta_generic_to_global(gptr)))
#define CP_COMMIT() asm volatile("cp.async.commit_group;")
#define CP_WAIT(n)  asm volatile("cp.async.wait_group %0;" :: "n"(n))

// ---------------------------------------------------------------------------
// K0: trig table. K1: hi/lo fp16 decomposition of x and Wqv^T.
// ---------------------------------------------------------------------------
__global__ void k_trig() {
    int p = blockIdx.x, i = threadIdx.x;
    double f = exp(-(double)i * (log(10000.0) / 31.0));
    double ang = (double)p * f;
    g_trig[p * 64 + i] = (float)sin(ang);
    g_trig[p * 64 + 32 + i] = (float)cos(ang);
}
__global__ __launch_bounds__(256) void k_decomp_x(const float* __restrict__ x) {
    int idx = blockIdx.x * 256 + threadIdx.x;
    float f = x[idx];
    __half h = __float2half_rn(f);
    g_xh[idx] = h;
    g_xl[idx] = __float2half_rn(f - __half2float(h));
}
__global__ __launch_bounds__(256) void k_decomp_w(const float* __restrict__ W) {
    int idx = blockIdx.x * 256 + threadIdx.x;
    int k = idx >> 11, n = idx & 2047;
    float f = W[idx];
    __half h = __float2half_rn(f);
    g_wh[n * 1024 + k] = h;
    g_wl[n * 1024 + k] = __float2half_rn(f - __half2float(h));
}

// ---------------------------------------------------------------------------
// K2: qv = x @ Wqv. smem cp.async + ldmatrix; q-blocks 3-product, v 2-product.
// ---------------------------------------------------------------------------
#define STAGE_BYTES 30720
#define QV_SMEM (2 * STAGE_BYTES)

__device__ __forceinline__ void stage_load(
    uint32_t sb, const __half* Ah, const __half* Al,
    const __half* Bh, const __half* Bl,
    size_t aRow, size_t bRow, int lda, int k0, int tid)
{
#pragma unroll
    for (int it = 0; it < 2; it++) {
        int idx = tid + it * 256;
        int r = idx >> 2, c = idx & 3;
        uint32_t so = r * 80 + c * 16;
        size_t go = (aRow + r) * (size_t)lda + k0 + c * 8;
        CP16(sb + so, Ah + go);
        CP16(sb + 10240 + so, Al + go);
    }
    {
        int r = tid >> 2, c = tid & 3;
        uint32_t so = r * 80 + c * 16;
        size_t go = (bRow + r) * (size_t)lda + k0 + c * 8;
        CP16(sb + 20480 + so, Bh + go);
        CP16(sb + 25600 + so, Bl + go);
    }
}
__device__ __forceinline__ void stage_mma(uint32_t sb, int wm, int wn, int lane,
                                          float acc[2][4][4], bool three)
{
    int rsel = lane & 15;
    uint32_t csel = ((lane >> 4) << 3);
#pragma unroll
    for (int kc = 0; kc < 32; kc += 16) {
        uint32_t colB = (kc + csel) * 2;
        uint32_t ah[2][4], al[2][4], bhf[2][4], blf[2][4];
#pragma unroll
        for (int mi = 0; mi < 2; mi++) {
            uint32_t ad = sb + (uint32_t)((wm + mi * 16 + rsel) * 80) + colB;
            ldsm4(ah[mi], ad);
            ldsm4(al[mi], ad + 10240);
        }
#pragma unroll
        for (int p = 0; p < 2; p++) {
            uint32_t bd = sb + 20480 + (uint32_t)((wn + p * 16 + rsel) * 80) + colB;
            ldsm4(bhf[p], bd);
            ldsm4(blf[p], bd + 5120);
        }
#pragma unroll
        for (int mi = 0; mi < 2; mi++)
#pragma unroll
            for (int ni = 0; ni < 4; ni++) {
                int p = ni >> 1, o = ni & 1;
                uint32_t bq[2]  = { bhf[p][o], bhf[p][o + 2] };
                uint32_t bql[2] = { blf[p][o], blf[p][o + 2] };
                mma_f16(acc[mi][ni], ah[mi], bq);
                mma_f16(acc[mi][ni], ah[mi], bql);
                if (three) mma_f16(acc[mi][ni], al[mi], bq);
            }
    }
}

__global__ __launch_bounds__(256, 2) void k_qv_mma(const float* __restrict__ rr) {
    extern __shared__ char dynsmem[];
    uint32_t sbase = smem_u32(dynsmem);
    int tid = threadIdx.x, wid = tid >> 5, lane = tid & 31;
    int wm = (wid >> 1) * 32, wn = (wid & 1) * 32;
    int g = lane >> 2, t = lane & 3;
    int brow = blockIdx.y * 128, bcol = blockIdx.x * 64;
    bool is_q = (bcol < 1024);

    float acc[2][4][4] = {};
    const int NS = 32;
    stage_load(sbase, g_xh, g_xl, g_wh, g_wl, brow, bcol, 1024, 0, tid);
    CP_COMMIT();
    for (int s = 0; s < NS; s++) {
        CP_WAIT(0);
        __syncthreads();
        if (s + 1 < NS) {
            stage_load(sbase + ((s + 1) & 1) * STAGE_BYTES, g_xh, g_xl, g_wh, g_wl,
                       brow, bcol, 1024, (s + 1) * 32, tid);
            CP_COMMIT();
        }
        stage_mma(sbase + (s & 1) * STAGE_BYTES, wm, wn, lane, acc, is_q);
    }

#pragma unroll
    for (int mi = 0; mi < 2; mi++)
#pragma unroll
        for (int ni = 0; ni < 4; ni++) {
            int row0 = brow + wm + mi * 16 + g;
            int cn = bcol + wn + ni * 8 + 2 * t;
            float2 v0 = make_float2(acc[mi][ni][0], acc[mi][ni][1]);
            float2 v1 = make_float2(acc[mi][ni][2], acc[mi][ni][3]);
            if (is_q) {
                float2 rb = *(const float2*)(rr + cn);
                v0.x += rb.x; v0.y += rb.y;
                v1.x += rb.x; v1.y += rb.y;
                *(float2*)&g_u[(size_t)row0 * 1024 + cn] = v0;
                *(float2*)&g_u[(size_t)(row0 + 8) * 1024 + cn] = v1;
            } else {
                *(float2*)&g_v[(size_t)row0 * 1024 + cn - 1024] = v0;
                *(float2*)&g_v[(size_t)(row0 + 8) * 1024 + cn - 1024] = v1;
            }
        }
}

// ---------------------------------------------------------------------------
// K3: V^T fp16 via smem tile transpose (both sides coalesced).
// ---------------------------------------------------------------------------
__global__ __launch_bounds__(256) void k_vt() {
    __shared__ float tile[64][65];
    int bh = blockIdx.y, tok0 = blockIdx.x * 64;
    int b = bh >> 4, h = bh & 15;
    int tid = threadIdx.x;
#pragma unroll
    for (int it = 0; it < 16; it++) {
        int idx = tid + it * 256;
        int r = idx >> 6, c = idx & 63;    // r = tok, c = d
        tile[r][c] = g_v[(size_t)(b * 1024 + tok0 + r) * 1024 + h * 64 + c];
    }
    __syncthreads();
#pragma unroll
    for (int it = 0; it < 16; it++) {
        int idx = tid + it * 256;
        int r = idx >> 6, c = idx & 63;    // r = d, c = tok
        g_vth[(size_t)(bh * 64 + r) * 1024 + tok0 + c] = __float2half_rn(tile[c][r]);
    }
}

// ---------------------------------------------------------------------------
// K4a/K4b: build Â and K̂ rows (fp16 hi/lo, 128-wide).
// ---------------------------------------------------------------------------
__global__ __launch_bounds__(256) void k_build_A(const float* __restrict__ rr,
                                                 const float* __restrict__ rw) {
    int idx = blockIdx.x * 256 + threadIdx.x;
    int bh = idx >> 10, q = idx & 1023;
    int b = bh >> 4, h = bh & 15;
    const float* up = g_u + (size_t)(b * 1024 + q) * 1024 + h * 64;
    __half* ah = g_Ah + (size_t)idx * 128;
    __half* al = g_Al + (size_t)idx * 128;
    const float* tg = g_trig + q * 64;
#pragma unroll 8
    for (int i = 0; i < 32; i++) {
        float u0 = up[i], u1 = up[32 + i];
        __half h0 = __float2half_rn(u0);
        ah[i] = h0; al[i] = __float2half_rn(u0 - __half2float(h0));
        __half h1 = __float2half_rn(u1);
        ah[32 + i] = h1; al[32 + i] = __float2half_rn(u1 - __half2float(h1));
        float w0 = u0 - rr[h * 64 + i] + rw[h * 64 + i];
        float w1 = u1 - rr[h * 64 + 32 + i] + rw[h * 64 + 32 + i];
        float sq = tg[i], cq = tg[32 + i];
        float a1 = w0 * cq + w1 * sq;
        float a2 = w1 * cq - w0 * sq;
        __half hh1 = __float2half_rn(a1);
        ah[64 + i] = hh1; al[64 + i] = __float2half_rn(a1 - __half2float(hh1));
        __half hh2 = __float2half_rn(a2);
        ah[96 + i] = hh2; al[96 + i] = __float2half_rn(a2 - __half2float(hh2));
    }
}
__global__ __launch_bounds__(256) void k_build_K(const float* __restrict__ x) {
    int idx = blockIdx.x * 256 + threadIdx.x;
    int bh = idx >> 10, k = idx & 1023;
    int b = bh >> 4, h = bh & 15;
    const float* xp = x + (size_t)(b * 1024 + k) * 1024 + h * 64;
    __half* kh = g_Kh + (size_t)idx * 128;
    __half* kl = g_Kl + (size_t)idx * 128;
    const float* tg = g_trig + k * 64;
#pragma unroll 8
    for (int i = 0; i < 32; i++) {
        float x0 = xp[i], x1 = xp[32 + i];
        __half h0 = __float2half_rn(x0);
        kh[i] = h0; kl[i] = __float2half_rn(x0 - __half2float(h0));
        __half h1 = __float2half_rn(x1);
        kh[32 + i] = h1; kl[32 + i] = __float2half_rn(x1 - __half2float(h1));
        float s = tg[i], c = tg[32 + i];
        __half h2 = __float2half_rn(s);
        kh[64 + i] = h2; kl[64 + i] = __float2half_rn(s - __half2float(h2));
        __half h3 = __float2half_rn(c);
        kh[96 + i] = h3; kl[96 + i] = __float2half_rn(c - __half2float(h3));
    }
}

// ---------------------------------------------------------------------------
// K5: flash attention. 128 q rows, 8 warps of 16q; 64-k tiles double-buffered.
// S = 3-product fp16 split; PV = 1-product (P fp16, V fp16). Single sync/iter.
//
// smem (80B rows, 32-col chunks):
//   Â  hi chunk c @ c*10240 (128 rows); lo +40960.            [0, 81920)
//   stage s @ 81920 + s*51200:
//     K̂ hi chunk c @ +c*5120 (64 rows); lo +20480.            (40960 B)
//     V  hi @ +40960: chunk c @ +c*5120 (64 d-rows x 32 tok). (10240 B)
// ---------------------------------------------------------------------------
#define FA_ACH 10240
#define FA_ALO 40960
#define FA_KBASE 81920
#define FA_KCH 5120
#define FA_KLO 20480
#define FA_VOFF 40960
#define FA_STAGE 51200
#define FA_SMEM (FA_KBASE + 2 * FA_STAGE)   // 184320

__device__ __forceinline__ void fa_load_kv(uint32_t sb, int bh, size_t kRow,
                                           int kb, int buf, int tid) {
    uint32_t st = sb + FA_KBASE + buf * FA_STAGE;
#pragma unroll
    for (int it = 0; it < 4; it++) {
        int idx = tid + it * 256;              // 0..1023
        int r = idx >> 4, cc = idx & 15;
        uint32_t so = (cc >> 2) * FA_KCH + r * 80 + (cc & 3) * 16;
        size_t go = (kRow + kb + r) * 128 + cc * 8;
        CP16(st + so, g_Kh + go);
        CP16(st + FA_KLO + so, g_Kl + go);
    }
    uint32_t stV = st + FA_VOFF;
#pragma unroll
    for (int it = 0; it < 2; it++) {
        int idx = tid + it * 256;              // 0..511
        int r = idx >> 3, cc = idx & 7;        // r: d-row 0..63
        int c = cc >> 2, c4 = cc & 3;
        uint32_t so = c * FA_KCH + r * 80 + c4 * 16;
        size_t go = (size_t)(bh * 64 + r) * 1024 + kb + c * 32 + c4 * 8;
        CP16(stV + so, g_vth + go);
    }
}

__global__ __launch_bounds__(256, 1) void k_flash(const int* __restrict__ mask,
                                                  float* __restrict__ out) {
    extern __shared__ char dynsmem[];
    __shared__ int msk[1024];
    uint32_t sb = smem_u32(dynsmem);
    int bh = blockIdx.y, b = bh >> 4, h = bh & 15;
    int brow = blockIdx.x * 128;
    int tid = threadIdx.x, wid = tid >> 5, lane = tid & 31;
    int wm = wid * 16;
    int g = lane >> 2, t = lane & 3;
    int rsel = lane & 15;
    uint32_t csel = ((lane >> 4) << 3);

    size_t aRow = (size_t)bh * 1024 + brow;
    size_t kRow = (size_t)bh * 1024;

    // ---- load Â (once) ----
#pragma unroll
    for (int it = 0; it < 8; it++) {
        int idx = tid + it * 256;
        int r = idx >> 4, cc = idx & 15;
        uint32_t so = (cc >> 2) * FA_ACH + r * 80 + (cc & 3) * 16;
        size_t go = (aRow + r) * 128 + cc * 8;
        CP16(sb + so, g_Ah + go);
        CP16(sb + FA_ALO + so, g_Al + go);
    }
    fa_load_kv(sb, bh, kRow, 0, 0, tid);
    CP_COMMIT();
    for (int i = tid; i < 1024; i += 256) msk[i] = mask[b * 1024 + i];

    float oacc[8][4] = {};
    float m0 = -CUDART_INF_F, m1 = -CUDART_INF_F, l0 = 0.0f, l1 = 0.0f;

    const int NT = 16;
    for (int kt = 0; kt < NT; kt++) {
        CP_WAIT(0);
        __syncthreads();
        if (kt + 1 < NT) {
            fa_load_kv(sb, bh, kRow, (kt + 1) * 64, (kt + 1) & 1, tid);
            CP_COMMIT();
        }

        // ---- S tile: 16q x 64k per warp, K=128 ----
        uint32_t Ks = sb + FA_KBASE + (kt & 1) * FA_STAGE;
        float sacc[8][4] = {};
#pragma unroll
        for (int ks = 0; ks < 8; ks++) {
            int c = ks >> 1;
            uint32_t colB = (((ks & 1) * 16) + csel) * 2;
            uint32_t ah[4], al[4], bhf[4][4], blf[4][4];
            uint32_t ad = sb + (uint32_t)(c * FA_ACH) + (uint32_t)((wm + rsel) * 80) + colB;
            ldsm4(ah, ad);
            ldsm4(al, ad + FA_ALO);
#pragma unroll
            for (int p = 0; p < 4; p++) {
                uint32_t kd = Ks + (uint32_t)(c * FA_KCH) + (uint32_t)((p * 16 + rsel) * 80) + colB;
                ldsm4(bhf[p], kd);
                ldsm4(blf[p], kd + FA_KLO);
            }
#pragma unroll
            for (int ni = 0; ni < 8; ni++) {
                int p = ni >> 1, o = ni & 1;
                uint32_t bq[2]  = { bhf[p][o], bhf[p][o + 2] };
                uint32_t bql[2] = { blf[p][o], blf[p][o + 2] };
                mma_f16(sacc[ni], ah, bq);
                mma_f16(sacc[ni], ah, bql);
                mma_f16(sacc[ni], al, bq);
            }
        }

        // ---- online softmax ----
        int kb = kt * 64;
        float tmax0 = -CUDART_INF_F, tmax1 = -CUDART_INF_F;
#pragma unroll
        for (int ni = 0; ni < 8; ni++) {
            int kc = kb + ni * 8 + 2 * t;
            if (msk[kc] == 0)     { sacc[ni][0] = -CUDART_INF_F; sacc[ni][2] = -CUDART_INF_F; }
            if (msk[kc + 1] == 0) { sacc[ni][1] = -CUDART_INF_F; sacc[ni][3] = -CUDART_INF_F; }
            tmax0 = fmaxf(tmax0, fmaxf(sacc[ni][0], sacc[ni][1]));
            tmax1 = fmaxf(tmax1, fmaxf(sacc[ni][2], sacc[ni][3]));
        }
        tmax0 = fmaxf(tmax0, __shfl_xor_sync(0xffffffffu, tmax0, 1));
        tmax0 = fmaxf(tmax0, __shfl_xor_sync(0xffffffffu, tmax0, 2));
        tmax1 = fmaxf(tmax1, __shfl_xor_sync(0xffffffffu, tmax1, 1));
        tmax1 = fmaxf(tmax1, __shfl_xor_sync(0xffffffffu, tmax1, 2));
        float nm0 = fmaxf(m0, tmax0), nm1 = fmaxf(m1, tmax1);
        float sc0 = __expf(m0 - nm0), sc1 = __expf(m1 - nm1);
        m0 = nm0; m1 = nm1;

        float rs0 = 0.0f, rs1 = 0.0f;
        uint32_t aPh[4][4];
#pragma unroll
        for (int ni = 0; ni < 8; ni++) {
            float p0 = __expf(sacc[ni][0] - nm0);
            float p1 = __expf(sacc[ni][1] - nm0);
            float p2 = __expf(sacc[ni][2] - nm1);
            float p3 = __expf(sacc[ni][3] - nm1);
            rs0 += p0 + p1;
            rs1 += p2 + p3;
            int c2 = ni >> 1, o = ni & 1;
            aPh[c2][o * 2 + 0] = packh2(p0, p1);
            aPh[c2][o * 2 + 1] = packh2(p2, p3);
        }
        rs0 += __shfl_xor_sync(0xffffffffu, rs0, 1);
        rs0 += __shfl_xor_sync(0xffffffffu, rs0, 2);
        rs1 += __shfl_xor_sync(0xffffffffu, rs1, 1);
        rs1 += __shfl_xor_sync(0xffffffffu, rs1, 2);
        l0 = l0 * sc0 + rs0;
        l1 = l1 * sc1 + rs1;
#pragma unroll
        for (int ni2 = 0; ni2 < 8; ni2++) {
            oacc[ni2][0] *= sc0; oacc[ni2][1] *= sc0;
            oacc[ni2][2] *= sc1; oacc[ni2][3] *= sc1;
        }

        // ---- PV: O += P @ V (single product, V fp16 from smem) ----
        uint32_t Vs = Ks + FA_VOFF;
#pragma unroll
        for (int c2 = 0; c2 < 4; c2++) {
            int c = c2 >> 1;
            uint32_t colB = (((c2 & 1) * 16) + csel) * 2;
            uint32_t bvh[4][4];
#pragma unroll
            for (int p = 0; p < 4; p++) {
                uint32_t vd = Vs + (uint32_t)(c * FA_KCH) + (uint32_t)((p * 16 + rsel) * 80) + colB;
                ldsm4(bvh[p], vd);
            }
#pragma unroll
            for (int ni2 = 0; ni2 < 8; ni2++) {
                int p = ni2 >> 1, o = ni2 & 1;
                uint32_t bq[2] = { bvh[p][o], bvh[p][o + 2] };
                mma_f16(oacc[ni2], aPh[c2], bq);
            }
        }
    }

    // ---- epilogue ----
    float inv0 = 1.0f / l0, inv1 = 1.0f / l1;
    int row0 = b * 1024 + brow + wm + g;
    int row1 = row0 + 8;
#pragma unroll
    for (int ni2 = 0; ni2 < 8; ni2++) {
        int cn = h * 64 + ni2 * 8 + 2 * t;
        *(float2*)&out[(size_t)row0 * 1024 + cn] =
            make_float2(oacc[ni2][0] * inv0, oacc[ni2][1] * inv0);
        *(float2*)&out[(size_t)row1 * 1024 + cn] =
            make_float2(oacc[ni2][2] * inv1, oacc[ni2][3] * inv1);
    }
}

// ---------------------------------------------------------------------------
extern "C" void kernel_launch(void* const* d_in, const int* in_sizes, int n_in,
                              void* d_out, int out_size) {
    (void)in_sizes; (void)n_in; (void)out_size;
    const float* x    = (const float*)d_in[0];
    const float* Wqv  = (const float*)d_in[1];
    const float* rr   = (const float*)d_in[2];
    const float* rw   = (const float*)d_in[3];
    const int*   mask = (const int*)d_in[4];
    float* out = (float*)d_out;

    cudaFuncSetAttribute(k_qv_mma, cudaFuncAttributeMaxDynamicSharedMemorySize, QV_SMEM);
    cudaFuncSetAttribute(k_flash,  cudaFuncAttributeMaxDynamicSharedMemorySize, FA_SMEM);

    k_trig<<<1024, 32>>>();
    k_decomp_x<<<16384, 256>>>(x);
    k_decomp_w<<<8192, 256>>>(Wqv);
    k_qv_mma<<<dim3(32, 32), 256, QV_SMEM>>>(rr);
    k_vt<<<dim3(16, 64), 256>>>();
    k_build_A<<<256, 256>>>(rr, rw);
    k_build_K<<<256, 256>>>(x);
    k_flash<<<dim3(8, 64), 256, FA_SMEM>>>(mask, out);
}

// round 12
// speedup vs baseline: 1.3074x; 1.1019x over previous
#include <cuda_runtime.h>
#include <cuda_fp16.h>
#include <math_constants.h>
#include <math.h>
#include <cstdint>

// B=4, L=1024, D=1024, H=16, HD=64.
// S[q,k] = (q+rr)·x_k + (q+rw)·pos[k-q+L] == Â[q]·K̂[k], K=128 (angle addition).
// R12: K̂ never materialized (content = x slices, trig = shared L2-hot table);
//      Â content = u (fp16 hi/lo from qv epilogue); build_A emits trig half only.

// ---------------------------------------------------------------------------
// Device scratch
// ---------------------------------------------------------------------------
__device__ __align__(16) __half g_xh[4096 * 1024];
__device__ __align__(16) __half g_xl[4096 * 1024];
__device__ __align__(16) __half g_wh[2048 * 1024];      // Wqv^T hi [n][k]
__device__ __align__(16) __half g_wl[2048 * 1024];
__device__ __align__(16) __half g_uh[4096 * 1024];      // u = q + rr, fp16 hi
__device__ __align__(16) __half g_ul[4096 * 1024];      // u lo
__device__ __align__(16) float g_v[4096 * 1024];        // v fp32
__device__ __align__(16) __half g_vth[64 * 64 * 1024];  // V^T fp16 [bh*64+d][tok]
__device__ __align__(16) float g_trig[1024 * 64];       // fp32 [p][i]=sin, [p][32+i]=cos
__device__ __align__(16) __half g_tgh[1024 * 64];       // fp16 hi of trig
__device__ __align__(16) __half g_tgl[1024 * 64];       // fp16 lo of trig
__device__ __align__(16) __half g_Ath[(size_t)64 * 1024 * 64];  // Â trig half hi
__device__ __align__(16) __half g_Atl[(size_t)64 * 1024 * 64];  // Â trig half lo

// ---------------------------------------------------------------------------
// helpers
// ---------------------------------------------------------------------------
__device__ __forceinline__ uint32_t smem_u32(const void* p) {
    uint32_t a;
    asm("{ .reg .u64 t; cvta.to.shared.u64 t, %1; cvt.u32.u64 %0, t; }" : "=r"(a) : "l"(p));
    return a;
}
__device__ __forceinline__ void mma_f16(float* c, const uint32_t* a, const uint32_t* b) {
    asm volatile(
        "mma.sync.aligned.m16n8k16.row.col.f32.f16.f16.f32 "
        "{%0,%1,%2,%3}, {%4,%5,%6,%7}, {%8,%9}, {%0,%1,%2,%3};"
        : "+f"(c[0]), "+f"(c[1]), "+f"(c[2]), "+f"(c[3])
        : "r"(a[0]), "r"(a[1]), "r"(a[2]), "r"(a[3]), "r"(b[0]), "r"(b[1]));
}
__device__ __forceinline__ void ldsm4(uint32_t* r, uint32_t addr) {
    asm volatile("ldmatrix.sync.aligned.m8n8.x4.shared.b16 {%0,%1,%2,%3}, [%4];"
        : "=r"(r[0]), "=r"(r[1]), "=r"(r[2]), "=r"(r[3]) : "r"(addr));
}
__device__ __forceinline__ uint32_t packh2(float e0, float e1) {
    __half2 h = __floats2half2_rn(e0, e1);
    return *(uint32_t*)&h;
}
#define CP16(saddr, gptr) \
    asm volatile("cp.async.ca.shared.global [%0], [%1], 16;" \
        :: "r"(saddr), "l"(__cvta_generic_to_global(gptr)))
#define CP_COMMIT() asm volatile("cp.async.commit_group;")
#define CP_WAIT(n)  asm volatile("cp.async.wait_group %0;" :: "n"(n))

// ---------------------------------------------------------------------------
// K0: trig tables. fp32 (for build_A math) + fp16 hi/lo (for flash K̂ trig).
// ---------------------------------------------------------------------------
__global__ void k_trig() {
    int p = blockIdx.x, i = threadIdx.x;
    double f = exp(-(double)i * (log(10000.0) / 31.0));
    double ang = (double)p * f;
    float s = (float)sin(ang), c = (float)cos(ang);
    g_trig[p * 64 + i] = s;
    g_trig[p * 64 + 32 + i] = c;
    __half sh = __float2half_rn(s), ch = __float2half_rn(c);
    g_tgh[p * 64 + i] = sh;
    g_tgh[p * 64 + 32 + i] = ch;
    g_tgl[p * 64 + i] = __float2half_rn(s - __half2float(sh));
    g_tgl[p * 64 + 32 + i] = __float2half_rn(c - __half2float(ch));
}
__global__ __launch_bounds__(256) void k_decomp_x(const float* __restrict__ x) {
    int idx = blockIdx.x * 256 + threadIdx.x;
    float f = x[idx];
    __half h = __float2half_rn(f);
    g_xh[idx] = h;
    g_xl[idx] = __float2half_rn(f - __half2float(h));
}
__global__ __launch_bounds__(256) void k_decomp_w(const float* __restrict__ W) {
    int idx = blockIdx.x * 256 + threadIdx.x;
    int k = idx >> 11, n = idx & 2047;
    float f = W[idx];
    __half h = __float2half_rn(f);
    g_wh[n * 1024 + k] = h;
    g_wl[n * 1024 + k] = __float2half_rn(f - __half2float(h));
}

// ---------------------------------------------------------------------------
// K2: qv = x @ Wqv. q-half 3-product, v-half 2-product. Epilogue: q -> uh/ul
// fp16 split; v -> g_v fp32.
// ---------------------------------------------------------------------------
#define STAGE_BYTES 30720
#define QV_SMEM (2 * STAGE_BYTES)

__device__ __forceinline__ void stage_load(
    uint32_t sb, const __half* Ah, const __half* Al,
    const __half* Bh, const __half* Bl,
    size_t aRow, size_t bRow, int lda, int k0, int tid)
{
#pragma unroll
    for (int it = 0; it < 2; it++) {
        int idx = tid + it * 256;
        int r = idx >> 2, c = idx & 3;
        uint32_t so = r * 80 + c * 16;
        size_t go = (aRow + r) * (size_t)lda + k0 + c * 8;
        CP16(sb + so, Ah + go);
        CP16(sb + 10240 + so, Al + go);
    }
    {
        int r = tid >> 2, c = tid & 3;
        uint32_t so = r * 80 + c * 16;
        size_t go = (bRow + r) * (size_t)lda + k0 + c * 8;
        CP16(sb + 20480 + so, Bh + go);
        CP16(sb + 25600 + so, Bl + go);
    }
}
__device__ __forceinline__ void stage_mma(uint32_t sb, int wm, int wn, int lane,
                                          float acc[2][4][4], bool three)
{
    int rsel = lane & 15;
    uint32_t csel = ((lane >> 4) << 3);
#pragma unroll
    for (int kc = 0; kc < 32; kc += 16) {
        uint32_t colB = (kc + csel) * 2;
        uint32_t ah[2][4], al[2][4], bhf[2][4], blf[2][4];
#pragma unroll
        for (int mi = 0; mi < 2; mi++) {
            uint32_t ad = sb + (uint32_t)((wm + mi * 16 + rsel) * 80) + colB;
            ldsm4(ah[mi], ad);
            ldsm4(al[mi], ad + 10240);
        }
#pragma unroll
        for (int p = 0; p < 2; p++) {
            uint32_t bd = sb + 20480 + (uint32_t)((wn + p * 16 + rsel) * 80) + colB;
            ldsm4(bhf[p], bd);
            ldsm4(blf[p], bd + 5120);
        }
#pragma unroll
        for (int mi = 0; mi < 2; mi++)
#pragma unroll
            for (int ni = 0; ni < 4; ni++) {
                int p = ni >> 1, o = ni & 1;
                uint32_t bq[2]  = { bhf[p][o], bhf[p][o + 2] };
                uint32_t bql[2] = { blf[p][o], blf[p][o + 2] };
                mma_f16(acc[mi][ni], ah[mi], bq);
                mma_f16(acc[mi][ni], ah[mi], bql);
                if (three) mma_f16(acc[mi][ni], al[mi], bq);
            }
    }
}

__global__ __launch_bounds__(256, 2) void k_qv_mma(const float* __restrict__ rr) {
    extern __shared__ char dynsmem[];
    uint32_t sbase = smem_u32(dynsmem);
    int tid = threadIdx.x, wid = tid >> 5, lane = tid & 31;
    int wm = (wid >> 1) * 32, wn = (wid & 1) * 32;
    int g = lane >> 2, t = lane & 3;
    int brow = blockIdx.y * 128, bcol = blockIdx.x * 64;
    bool is_q = (bcol < 1024);

    float acc[2][4][4] = {};
    const int NS = 32;
    stage_load(sbase, g_xh, g_xl, g_wh, g_wl, brow, bcol, 1024, 0, tid);
    CP_COMMIT();
    for (int s = 0; s < NS; s++) {
        CP_WAIT(0);
        __syncthreads();
        if (s + 1 < NS) {
            stage_load(sbase + ((s + 1) & 1) * STAGE_BYTES, g_xh, g_xl, g_wh, g_wl,
                       brow, bcol, 1024, (s + 1) * 32, tid);
            CP_COMMIT();
        }
        stage_mma(sbase + (s & 1) * STAGE_BYTES, wm, wn, lane, acc, is_q);
    }

#pragma unroll
    for (int mi = 0; mi < 2; mi++)
#pragma unroll
        for (int ni = 0; ni < 4; ni++) {
            int row0 = brow + wm + mi * 16 + g;
            int cn = bcol + wn + ni * 8 + 2 * t;
            float2 v0 = make_float2(acc[mi][ni][0], acc[mi][ni][1]);
            float2 v1 = make_float2(acc[mi][ni][2], acc[mi][ni][3]);
            if (is_q) {
                float2 rb = *(const float2*)(rr + cn);
                v0.x += rb.x; v0.y += rb.y;
                v1.x += rb.x; v1.y += rb.y;
                __half2 h0 = __floats2half2_rn(v0.x, v0.y);
                __half2 l0 = __floats2half2_rn(v0.x - __half2float(h0.x),
                                               v0.y - __half2float(h0.y));
                __half2 h1 = __floats2half2_rn(v1.x, v1.y);
                __half2 l1 = __floats2half2_rn(v1.x - __half2float(h1.x),
                                               v1.y - __half2float(h1.y));
                *(__half2*)&g_uh[(size_t)row0 * 1024 + cn] = h0;
                *(__half2*)&g_ul[(size_t)row0 * 1024 + cn] = l0;
                *(__half2*)&g_uh[(size_t)(row0 + 8) * 1024 + cn] = h1;
                *(__half2*)&g_ul[(size_t)(row0 + 8) * 1024 + cn] = l1;
            } else {
                *(float2*)&g_v[(size_t)row0 * 1024 + cn - 1024] = v0;
                *(float2*)&g_v[(size_t)(row0 + 8) * 1024 + cn - 1024] = v1;
            }
        }
}

// ---------------------------------------------------------------------------
// K3: V^T fp16 via smem tile transpose.
// ---------------------------------------------------------------------------
__global__ __launch_bounds__(256) void k_vt() {
    __shared__ float tile[64][65];
    int bh = blockIdx.y, tok0 = blockIdx.x * 64;
    int b = bh >> 4, h = bh & 15;
    int tid = threadIdx.x;
#pragma unroll
    for (int it = 0; it < 16; it++) {
        int idx = tid + it * 256;
        int r = idx >> 6, c = idx & 63;
        tile[r][c] = g_v[(size_t)(b * 1024 + tok0 + r) * 1024 + h * 64 + c];
    }
    __syncthreads();
#pragma unroll
    for (int it = 0; it < 16; it++) {
        int idx = tid + it * 256;
        int r = idx >> 6, c = idx & 63;
        g_vth[(size_t)(bh * 64 + r) * 1024 + tok0 + c] = __float2half_rn(tile[c][r]);
    }
}

// ---------------------------------------------------------------------------
// K4: build Â trig half only: cols j=i -> a1, j=32+i -> a2 (fp16 hi/lo).
// w = u - rr + rw with u = uh + ul (exact).
// ---------------------------------------------------------------------------
__global__ __launch_bounds__(256) void k_build_A(const float* __restrict__ rr,
                                                 const float* __restrict__ rw) {
    int idx = blockIdx.x * 256 + threadIdx.x;     // bh*1024 + q
    int bh = idx >> 10, q = idx & 1023;
    int b = bh >> 4, h = bh & 15;
    const __half* uhp = g_uh + (size_t)(b * 1024 + q) * 1024 + h * 64;
    const __half* ulp = g_ul + (size_t)(b * 1024 + q) * 1024 + h * 64;
    __half* ah = g_Ath + (size_t)idx * 64;
    __half* al = g_Atl + (size_t)idx * 64;
    const float* tg = g_trig + q * 64;
#pragma unroll 8
    for (int i = 0; i < 32; i++) {
        float u0 = __half2float(uhp[i]) + __half2float(ulp[i]);
        float u1 = __half2float(uhp[32 + i]) + __half2float(ulp[32 + i]);
        float w0 = u0 - rr[h * 64 + i] + rw[h * 64 + i];
        float w1 = u1 - rr[h * 64 + 32 + i] + rw[h * 64 + 32 + i];
        float sq = tg[i], cq = tg[32 + i];
        float a1 = w0 * cq + w1 * sq;
        float a2 = w1 * cq - w0 * sq;
        __half hh1 = __float2half_rn(a1);
        ah[i] = hh1; al[i] = __float2half_rn(a1 - __half2float(hh1));
        __half hh2 = __float2half_rn(a2);
        ah[32 + i] = hh2; al[32 + i] = __float2half_rn(a2 - __half2float(hh2));
    }
}

// ---------------------------------------------------------------------------
// K5: flash attention. 128 q rows, 8 warps of 16q; 64-k tiles double-buffered.
// Â content from g_uh/g_ul, trig from g_Ath/g_Atl; K̂ content from g_xh/g_xl,
// trig from g_tgh/g_tgl (L2-hot). S 3-product; PV 1-product.
//
// smem (80B rows, 32-halves chunks):
//   Â  hi chunk c @ c*10240 (128 rows); lo +40960.            [0, 81920)
//   stage s @ 81920 + s*51200:
//     K̂ hi chunk c @ +c*5120 (64 rows); lo +20480.            (40960 B)
//     V  hi @ +40960: chunk c @ +c*5120 (64 d-rows x 32 tok). (10240 B)
// ---------------------------------------------------------------------------
#define FA_ACH 10240
#define FA_ALO 40960
#define FA_KBASE 81920
#define FA_KCH 5120
#define FA_KLO 20480
#define FA_VOFF 40960
#define FA_STAGE 51200
#define FA_SMEM (FA_KBASE + 2 * FA_STAGE)   // 184320

__device__ __forceinline__ void fa_load_kv(uint32_t sb, int bh, int b, int h,
                                           int kb, int buf, int tid) {
    uint32_t st = sb + FA_KBASE + buf * FA_STAGE;
#pragma unroll
    for (int it = 0; it < 4; it++) {
        int idx = tid + it * 256;              // 0..1023 = 64 rows x 16 cc
        int r = idx >> 4, cc = idx & 15;
        uint32_t so = (cc >> 2) * FA_KCH + r * 80 + (cc & 3) * 16;
        if (cc < 8) {
            size_t go = (size_t)(b * 1024 + kb + r) * 1024 + h * 64
                      + (cc >> 2) * 32 + (cc & 3) * 8;
            CP16(st + so, g_xh + go);
            CP16(st + FA_KLO + so, g_xl + go);
        } else {
            size_t go = (size_t)(kb + r) * 64 + ((cc >> 2) - 2) * 32 + (cc & 3) * 8;
            CP16(st + so, g_tgh + go);
            CP16(st + FA_KLO + so, g_tgl + go);
        }
    }
    uint32_t stV = st + FA_VOFF;
#pragma unroll
    for (int it = 0; it < 2; it++) {
        int idx = tid + it * 256;              // 0..511
        int r = idx >> 3, cc = idx & 7;        // r: d-row 0..63
        int c = cc >> 2, c4 = cc & 3;
        uint32_t so = c * FA_KCH + r * 80 + c4 * 16;
        size_t go = (size_t)(bh * 64 + r) * 1024 + kb + c * 32 + c4 * 8;
        CP16(stV + so, g_vth + go);
    }
}

__global__ __launch_bounds__(256, 1) void k_flash(const int* __restrict__ mask,
                                                  float* __restrict__ out) {
    extern __shared__ char dynsmem[];
    __shared__ int msk[1024];
    uint32_t sb = smem_u32(dynsmem);
    int bh = blockIdx.y, b = bh >> 4, h = bh & 15;
    int brow = blockIdx.x * 128;
    int tid = threadIdx.x, wid = tid >> 5, lane = tid & 31;
    int wm = wid * 16;
    int g = lane >> 2, t = lane & 3;
    int rsel = lane & 15;
    uint32_t csel = ((lane >> 4) << 3);

    // ---- load Â (once): content chunks 0-1 from uh/ul, trig chunks 2-3 ----
#pragma unroll
    for (int it = 0; it < 8; it++) {
        int idx = tid + it * 256;              // 0..2047 = 128 rows x 16 cc
        int r = idx >> 4, cc = idx & 15;
        uint32_t so = (cc >> 2) * FA_ACH + r * 80 + (cc & 3) * 16;
        if (cc < 8) {
            size_t go = (size_t)(b * 1024 + brow + r) * 1024 + h * 64
                      + (cc >> 2) * 32 + (cc & 3) * 8;
            CP16(sb + so, g_uh + go);
            CP16(sb + FA_ALO + so, g_ul + go);
        } else {
            size_t go = ((size_t)bh * 1024 + brow + r) * 64
                      + ((cc >> 2) - 2) * 32 + (cc & 3) * 8;
            CP16(sb + so, g_Ath + go);
            CP16(sb + FA_ALO + so, g_Atl + go);
        }
    }
    fa_load_kv(sb, bh, b, h, 0, 0, tid);
    CP_COMMIT();
    for (int i = tid; i < 1024; i += 256) msk[i] = mask[b * 1024 + i];

    float oacc[8][4] = {};
    float m0 = -CUDART_INF_F, m1 = -CUDART_INF_F, l0 = 0.0f, l1 = 0.0f;

    const int NT = 16;
    for (int kt = 0; kt < NT; kt++) {
        CP_WAIT(0);
        __syncthreads();
        if (kt + 1 < NT) {
            fa_load_kv(sb, bh, b, h, (kt + 1) * 64, (kt + 1) & 1, tid);
            CP_COMMIT();
        }

        // ---- S tile: 16q x 64k per warp, K=128 ----
        uint32_t Ks = sb + FA_KBASE + (kt & 1) * FA_STAGE;
        float sacc[8][4] = {};
#pragma unroll
        for (int ks = 0; ks < 8; ks++) {
            int c = ks >> 1;
            uint32_t colB = (((ks & 1) * 16) + csel) * 2;
            uint32_t ah[4], al[4], bhf[4][4], blf[4][4];
            uint32_t ad = sb + (uint32_t)(c * FA_ACH) + (uint32_t)((wm + rsel) * 80) + colB;
            ldsm4(ah, ad);
            ldsm4(al, ad + FA_ALO);
#pragma unroll
            for (int p = 0; p < 4; p++) {
                uint32_t kd = Ks + (uint32_t)(c * FA_KCH) + (uint32_t)((p * 16 + rsel) * 80) + colB;
                ldsm4(bhf[p], kd);
                ldsm4(blf[p], kd + FA_KLO);
            }
#pragma unroll
            for (int ni = 0; ni < 8; ni++) {
                int p = ni >> 1, o = ni & 1;
                uint32_t bq[2]  = { bhf[p][o], bhf[p][o + 2] };
                uint32_t bql[2] = { blf[p][o], blf[p][o + 2] };
                mma_f16(sacc[ni], ah, bq);
                mma_f16(sacc[ni], ah, bql);
                mma_f16(sacc[ni], al, bq);
            }
        }

        // ---- online softmax ----
        int kb = kt * 64;
        float tmax0 = -CUDART_INF_F, tmax1 = -CUDART_INF_F;
#pragma unroll
        for (int ni = 0; ni < 8; ni++) {
            int kc = kb + ni * 8 + 2 * t;
            if (msk[kc] == 0)     { sacc[ni][0] = -CUDART_INF_F; sacc[ni][2] = -CUDART_INF_F; }
            if (msk[kc + 1] == 0) { sacc[ni][1] = -CUDART_INF_F; sacc[ni][3] = -CUDART_INF_F; }
            tmax0 = fmaxf(tmax0, fmaxf(sacc[ni][0], sacc[ni][1]));
            tmax1 = fmaxf(tmax1, fmaxf(sacc[ni][2], sacc[ni][3]));
        }
        tmax0 = fmaxf(tmax0, __shfl_xor_sync(0xffffffffu, tmax0, 1));
        tmax0 = fmaxf(tmax0, __shfl_xor_sync(0xffffffffu, tmax0, 2));
        tmax1 = fmaxf(tmax1, __shfl_xor_sync(0xffffffffu, tmax1, 1));
        tmax1 = fmaxf(tmax1, __shfl_xor_sync(0xffffffffu, tmax1, 2));
        float nm0 = fmaxf(m0, tmax0), nm1 = fmaxf(m1, tmax1);
        float sc0 = __expf(m0 - nm0), sc1 = __expf(m1 - nm1);
        m0 = nm0; m1 = nm1;

        float rs0 = 0.0f, rs1 = 0.0f;
        uint32_t aPh[4][4];
#pragma unroll
        for (int ni = 0; ni < 8; ni++) {
            float p0 = __expf(sacc[ni][0] - nm0);
            float p1 = __expf(sacc[ni][1] - nm0);
            float p2 = __expf(sacc[ni][2] - nm1);
            float p3 = __expf(sacc[ni][3] - nm1);
            rs0 += p0 + p1;
            rs1 += p2 + p3;
            int c2 = ni >> 1, o = ni & 1;
            aPh[c2][o * 2 + 0] = packh2(p0, p1);
            aPh[c2][o * 2 + 1] = packh2(p2, p3);
        }
        rs0 += __shfl_xor_sync(0xffffffffu, rs0, 1);
        rs0 += __shfl_xor_sync(0xffffffffu, rs0, 2);
        rs1 += __shfl_xor_sync(0xffffffffu, rs1, 1);
        rs1 += __shfl_xor_sync(0xffffffffu, rs1, 2);
        l0 = l0 * sc0 + rs0;
        l1 = l1 * sc1 + rs1;
#pragma unroll
        for (int ni2 = 0; ni2 < 8; ni2++) {
            oacc[ni2][0] *= sc0; oacc[ni2][1] *= sc0;
            oacc[ni2][2] *= sc1; oacc[ni2][3] *= sc1;
        }

        // ---- PV: O += P @ V (single product) ----
        uint32_t Vs = Ks + FA_VOFF;
#pragma unroll
        for (int c2 = 0; c2 < 4; c2++) {
            int c = c2 >> 1;
            uint32_t colB = (((c2 & 1) * 16) + csel) * 2;
            uint32_t bvh[4][4];
#pragma unroll
            for (int p = 0; p < 4; p++) {
                uint32_t vd = Vs + (uint32_t)(c * FA_KCH) + (uint32_t)((p * 16 + rsel) * 80) + colB;
                ldsm4(bvh[p], vd);
            }
#pragma unroll
            for (int ni2 = 0; ni2 < 8; ni2++) {
                int p = ni2 >> 1, o = ni2 & 1;
                uint32_t bq[2] = { bvh[p][o], bvh[p][o + 2] };
                mma_f16(oacc[ni2], aPh[c2], bq);
            }
        }
    }

    // ---- epilogue ----
    float inv0 = 1.0f / l0, inv1 = 1.0f / l1;
    int row0 = b * 1024 + brow + wm + g;
    int row1 = row0 + 8;
#pragma unroll
    for (int ni2 = 0; ni2 < 8; ni2++) {
        int cn = h * 64 + ni2 * 8 + 2 * t;
        *(float2*)&out[(size_t)row0 * 1024 + cn] =
            make_float2(oacc[ni2][0] * inv0, oacc[ni2][1] * inv0);
        *(float2*)&out[(size_t)row1 * 1024 + cn] =
            make_float2(oacc[ni2][2] * inv1, oacc[ni2][3] * inv1);
    }
}

// ---------------------------------------------------------------------------
extern "C" void kernel_launch(void* const* d_in, const int* in_sizes, int n_in,
                              void* d_out, int out_size) {
    (void)in_sizes; (void)n_in; (void)out_size;
    const float* x    = (const float*)d_in[0];
    const float* Wqv  = (const float*)d_in[1];
    const float* rr   = (const float*)d_in[2];
    const float* rw   = (const float*)d_in[3];
    const int*   mask = (const int*)d_in[4];
    float* out = (float*)d_out;

    cudaFuncSetAttribute(k_qv_mma, cudaFuncAttributeMaxDynamicSharedMemorySize, QV_SMEM);
    cudaFuncSetAttribute(k_flash,  cudaFuncAttributeMaxDynamicSharedMemorySize, FA_SMEM);

    k_trig<<<1024, 32>>>();
    k_decomp_x<<<16384, 256>>>(x);
    k_decomp_w<<<8192, 256>>>(Wqv);
    k_qv_mma<<<dim3(32, 32), 256, QV_SMEM>>>(rr);
    k_vt<<<dim3(16, 64), 256>>>();
    k_build_A<<<256, 256>>>(rr, rw);
    k_flash<<<dim3(8, 64), 256, FA_SMEM>>>(mask, out);
}

// round 13
// speedup vs baseline: 1.3196x; 1.0094x over previous
#include <cuda_runtime.h>
#include <cuda_fp16.h>
#include <math_constants.h>
#include <math.h>
#include <cstdint>

// B=4, L=1024, D=1024, H=16, HD=64.
// S[q,k] = (q+rr)·x_k + (q+rw)·pos[k-q+L] == Â[q]·K̂[k], K=128 (angle addition).
// R13: v-half single-product; fused prep kernels (5 launches total).

// ---------------------------------------------------------------------------
// Device scratch
// ---------------------------------------------------------------------------
__device__ __align__(16) __half g_xh[4096 * 1024];
__device__ __align__(16) __half g_xl[4096 * 1024];
__device__ __align__(16) __half g_wh[2048 * 1024];      // Wqv^T hi [n][k]
__device__ __align__(16) __half g_wl[2048 * 1024];
__device__ __align__(16) __half g_uh[4096 * 1024];      // u = q + rr, fp16 hi
__device__ __align__(16) __half g_ul[4096 * 1024];      // u lo
__device__ __align__(16) float g_v[4096 * 1024];        // v fp32
__device__ __align__(16) __half g_vth[64 * 64 * 1024];  // V^T fp16 [bh*64+d][tok]
__device__ __align__(16) float g_trig[1024 * 64];       // fp32 [p][i]=sin, [p][32+i]=cos
__device__ __align__(16) __half g_tgh[1024 * 64];       // fp16 hi of trig
__device__ __align__(16) __half g_tgl[1024 * 64];       // fp16 lo of trig
__device__ __align__(16) __half g_Ath[(size_t)64 * 1024 * 64];  // Â trig half hi
__device__ __align__(16) __half g_Atl[(size_t)64 * 1024 * 64];  // Â trig half lo

// ---------------------------------------------------------------------------
// helpers
// ---------------------------------------------------------------------------
__device__ __forceinline__ uint32_t smem_u32(const void* p) {
    uint32_t a;
    asm("{ .reg .u64 t; cvta.to.shared.u64 t, %1; cvt.u32.u64 %0, t; }" : "=r"(a) : "l"(p));
    return a;
}
__device__ __forceinline__ void mma_f16(float* c, const uint32_t* a, const uint32_t* b) {
    asm volatile(
        "mma.sync.aligned.m16n8k16.row.col.f32.f16.f16.f32 "
        "{%0,%1,%2,%3}, {%4,%5,%6,%7}, {%8,%9}, {%0,%1,%2,%3};"
        : "+f"(c[0]), "+f"(c[1]), "+f"(c[2]), "+f"(c[3])
        : "r"(a[0]), "r"(a[1]), "r"(a[2]), "r"(a[3]), "r"(b[0]), "r"(b[1]));
}
__device__ __forceinline__ void ldsm4(uint32_t* r, uint32_t addr) {
    asm volatile("ldmatrix.sync.aligned.m8n8.x4.shared.b16 {%0,%1,%2,%3}, [%4];"
        : "=r"(r[0]), "=r"(r[1]), "=r"(r[2]), "=r"(r[3]) : "r"(addr));
}
__device__ __forceinline__ uint32_t packh2(float e0, float e1) {
    __half2 h = __floats2half2_rn(e0, e1);
    return *(uint32_t*)&h;
}
#define CP16(saddr, gptr) \
    asm volatile("cp.async.ca.shared.global [%0], [%1], 16;" \
        :: "r"(saddr), "l"(__cvta_generic_to_global(gptr)))
#define CP_COMMIT() asm volatile("cp.async.commit_group;")
#define CP_WAIT(n)  asm volatile("cp.async.wait_group %0;" :: "n"(n))

// ---------------------------------------------------------------------------
// K0: trig tables (fp32 + fp16 hi/lo).
// ---------------------------------------------------------------------------
__global__ void k_trig() {
    int p = blockIdx.x, i = threadIdx.x;
    double f = exp(-(double)i * (log(10000.0) / 31.0));
    double ang = (double)p * f;
    float s = (float)sin(ang), c = (float)cos(ang);
    g_trig[p * 64 + i] = s;
    g_trig[p * 64 + 32 + i] = c;
    __half sh = __float2half_rn(s), ch = __float2half_rn(c);
    g_tgh[p * 64 + i] = sh;
    g_tgh[p * 64 + 32 + i] = ch;
    g_tgl[p * 64 + i] = __float2half_rn(s - __half2float(sh));
    g_tgl[p * 64 + 32 + i] = __float2half_rn(c - __half2float(ch));
}

// ---------------------------------------------------------------------------
// K1 (fused): hi/lo fp16 decomposition of x (blocks < 16384) and Wqv^T.
// ---------------------------------------------------------------------------
__global__ __launch_bounds__(256) void k_decomp(const float* __restrict__ x,
                                                const float* __restrict__ W) {
    int bid = blockIdx.x;
    if (bid < 16384) {
        int idx = bid * 256 + threadIdx.x;
        float f = x[idx];
        __half h = __float2half_rn(f);
        g_xh[idx] = h;
        g_xl[idx] = __float2half_rn(f - __half2float(h));
    } else {
        int idx = (bid - 16384) * 256 + threadIdx.x;
        int k = idx >> 11, n = idx & 2047;
        float f = W[idx];
        __half h = __float2half_rn(f);
        g_wh[n * 1024 + k] = h;
        g_wl[n * 1024 + k] = __float2half_rn(f - __half2float(h));
    }
}

// ---------------------------------------------------------------------------
// K2: qv = x @ Wqv. q-half 3-product, v-half 1-product (xh·Wh).
// Epilogue: q -> uh/ul fp16 split; v -> g_v fp32.
// ---------------------------------------------------------------------------
#define STAGE_BYTES 30720
#define QV_SMEM (2 * STAGE_BYTES)

__device__ __forceinline__ void stage_load(
    uint32_t sb, const __half* Ah, const __half* Al,
    const __half* Bh, const __half* Bl,
    size_t aRow, size_t bRow, int lda, int k0, int tid, bool lo)
{
#pragma unroll
    for (int it = 0; it < 2; it++) {
        int idx = tid + it * 256;
        int r = idx >> 2, c = idx & 3;
        uint32_t so = r * 80 + c * 16;
        size_t go = (aRow + r) * (size_t)lda + k0 + c * 8;
        CP16(sb + so, Ah + go);
        if (lo) CP16(sb + 10240 + so, Al + go);
    }
    {
        int r = tid >> 2, c = tid & 3;
        uint32_t so = r * 80 + c * 16;
        size_t go = (bRow + r) * (size_t)lda + k0 + c * 8;
        CP16(sb + 20480 + so, Bh + go);
        if (lo) CP16(sb + 25600 + so, Bl + go);
    }
}
__device__ __forceinline__ void stage_mma(uint32_t sb, int wm, int wn, int lane,
                                          float acc[2][4][4], bool three)
{
    int rsel = lane & 15;
    uint32_t csel = ((lane >> 4) << 3);
#pragma unroll
    for (int kc = 0; kc < 32; kc += 16) {
        uint32_t colB = (kc + csel) * 2;
        uint32_t ah[2][4], al[2][4], bhf[2][4], blf[2][4];
#pragma unroll
        for (int mi = 0; mi < 2; mi++) {
            uint32_t ad = sb + (uint32_t)((wm + mi * 16 + rsel) * 80) + colB;
            ldsm4(ah[mi], ad);
            if (three) ldsm4(al[mi], ad + 10240);
        }
#pragma unroll
        for (int p = 0; p < 2; p++) {
            uint32_t bd = sb + 20480 + (uint32_t)((wn + p * 16 + rsel) * 80) + colB;
            ldsm4(bhf[p], bd);
            if (three) ldsm4(blf[p], bd + 5120);
        }
#pragma unroll
        for (int mi = 0; mi < 2; mi++)
#pragma unroll
            for (int ni = 0; ni < 4; ni++) {
                int p = ni >> 1, o = ni & 1;
                uint32_t bq[2] = { bhf[p][o], bhf[p][o + 2] };
                mma_f16(acc[mi][ni], ah[mi], bq);
                if (three) {
                    uint32_t bql[2] = { blf[p][o], blf[p][o + 2] };
                    mma_f16(acc[mi][ni], ah[mi], bql);
                    mma_f16(acc[mi][ni], al[mi], bq);
                }
            }
    }
}

__global__ __launch_bounds__(256, 2) void k_qv_mma(const float* __restrict__ rr) {
    extern __shared__ char dynsmem[];
    uint32_t sbase = smem_u32(dynsmem);
    int tid = threadIdx.x, wid = tid >> 5, lane = tid & 31;
    int wm = (wid >> 1) * 32, wn = (wid & 1) * 32;
    int g = lane >> 2, t = lane & 3;
    int brow = blockIdx.y * 128, bcol = blockIdx.x * 64;
    bool is_q = (bcol < 1024);

    float acc[2][4][4] = {};
    const int NS = 32;
    stage_load(sbase, g_xh, g_xl, g_wh, g_wl, brow, bcol, 1024, 0, tid, is_q);
    CP_COMMIT();
    for (int s = 0; s < NS; s++) {
        CP_WAIT(0);
        __syncthreads();
        if (s + 1 < NS) {
            stage_load(sbase + ((s + 1) & 1) * STAGE_BYTES, g_xh, g_xl, g_wh, g_wl,
                       brow, bcol, 1024, (s + 1) * 32, tid, is_q);
            CP_COMMIT();
        }
        stage_mma(sbase + (s & 1) * STAGE_BYTES, wm, wn, lane, acc, is_q);
    }

#pragma unroll
    for (int mi = 0; mi < 2; mi++)
#pragma unroll
        for (int ni = 0; ni < 4; ni++) {
            int row0 = brow + wm + mi * 16 + g;
            int cn = bcol + wn + ni * 8 + 2 * t;
            float2 v0 = make_float2(acc[mi][ni][0], acc[mi][ni][1]);
            float2 v1 = make_float2(acc[mi][ni][2], acc[mi][ni][3]);
            if (is_q) {
                float2 rb = *(const float2*)(rr + cn);
                v0.x += rb.x; v0.y += rb.y;
                v1.x += rb.x; v1.y += rb.y;
                __half2 h0 = __floats2half2_rn(v0.x, v0.y);
                __half2 l0 = __floats2half2_rn(v0.x - __half2float(h0.x),
                                               v0.y - __half2float(h0.y));
                __half2 h1 = __floats2half2_rn(v1.x, v1.y);
                __half2 l1 = __floats2half2_rn(v1.x - __half2float(h1.x),
                                               v1.y - __half2float(h1.y));
                *(__half2*)&g_uh[(size_t)row0 * 1024 + cn] = h0;
                *(__half2*)&g_ul[(size_t)row0 * 1024 + cn] = l0;
                *(__half2*)&g_uh[(size_t)(row0 + 8) * 1024 + cn] = h1;
                *(__half2*)&g_ul[(size_t)(row0 + 8) * 1024 + cn] = l1;
            } else {
                *(float2*)&g_v[(size_t)row0 * 1024 + cn - 1024] = v0;
                *(float2*)&g_v[(size_t)(row0 + 8) * 1024 + cn - 1024] = v1;
            }
        }
}

// ---------------------------------------------------------------------------
// K3 (fused): blocks < 1024 -> V^T transpose; blocks >= 1024 -> build Â trig.
// ---------------------------------------------------------------------------
__global__ __launch_bounds__(256) void k_prep2(const float* __restrict__ rr,
                                               const float* __restrict__ rw) {
    int bid = blockIdx.x;
    if (bid < 1024) {
        __shared__ float tile[64][65];
        int bh = bid >> 4, tok0 = (bid & 15) * 64;
        int b = bh >> 4, h = bh & 15;
        int tid = threadIdx.x;
#pragma unroll
        for (int it = 0; it < 16; it++) {
            int idx = tid + it * 256;
            int r = idx >> 6, c = idx & 63;
            tile[r][c] = g_v[(size_t)(b * 1024 + tok0 + r) * 1024 + h * 64 + c];
        }
        __syncthreads();
#pragma unroll
        for (int it = 0; it < 16; it++) {
            int idx = tid + it * 256;
            int r = idx >> 6, c = idx & 63;
            g_vth[(size_t)(bh * 64 + r) * 1024 + tok0 + c] = __float2half_rn(tile[c][r]);
        }
    } else {
        int idx = (bid - 1024) * 256 + threadIdx.x;   // bh*1024 + q
        int bh = idx >> 10, q = idx & 1023;
        int b = bh >> 4, h = bh & 15;
        const __half* uhp = g_uh + (size_t)(b * 1024 + q) * 1024 + h * 64;
        const __half* ulp = g_ul + (size_t)(b * 1024 + q) * 1024 + h * 64;
        __half* ah = g_Ath + (size_t)idx * 64;
        __half* al = g_Atl + (size_t)idx * 64;
        const float* tg = g_trig + q * 64;
#pragma unroll 8
        for (int i = 0; i < 32; i++) {
            float u0 = __half2float(uhp[i]) + __half2float(ulp[i]);
            float u1 = __half2float(uhp[32 + i]) + __half2float(ulp[32 + i]);
            float w0 = u0 - rr[h * 64 + i] + rw[h * 64 + i];
            float w1 = u1 - rr[h * 64 + 32 + i] + rw[h * 64 + 32 + i];
            float sq = tg[i], cq = tg[32 + i];
            float a1 = w0 * cq + w1 * sq;
            float a2 = w1 * cq - w0 * sq;
            __half hh1 = __float2half_rn(a1);
            ah[i] = hh1; al[i] = __float2half_rn(a1 - __half2float(hh1));
            __half hh2 = __float2half_rn(a2);
            ah[32 + i] = hh2; al[32 + i] = __float2half_rn(a2 - __half2float(hh2));
        }
    }
}

// ---------------------------------------------------------------------------
// K5: flash attention (unchanged from R12).
// ---------------------------------------------------------------------------
#define FA_ACH 10240
#define FA_ALO 40960
#define FA_KBASE 81920
#define FA_KCH 5120
#define FA_KLO 20480
#define FA_VOFF 40960
#define FA_STAGE 51200
#define FA_SMEM (FA_KBASE + 2 * FA_STAGE)   // 184320

__device__ __forceinline__ void fa_load_kv(uint32_t sb, int bh, int b, int h,
                                           int kb, int buf, int tid) {
    uint32_t st = sb + FA_KBASE + buf * FA_STAGE;
#pragma unroll
    for (int it = 0; it < 4; it++) {
        int idx = tid + it * 256;
        int r = idx >> 4, cc = idx & 15;
        uint32_t so = (cc >> 2) * FA_KCH + r * 80 + (cc & 3) * 16;
        if (cc < 8) {
            size_t go = (size_t)(b * 1024 + kb + r) * 1024 + h * 64
                      + (cc >> 2) * 32 + (cc & 3) * 8;
            CP16(st + so, g_xh + go);
            CP16(st + FA_KLO + so, g_xl + go);
        } else {
            size_t go = (size_t)(kb + r) * 64 + ((cc >> 2) - 2) * 32 + (cc & 3) * 8;
            CP16(st + so, g_tgh + go);
            CP16(st + FA_KLO + so, g_tgl + go);
        }
    }
    uint32_t stV = st + FA_VOFF;
#pragma unroll
    for (int it = 0; it < 2; it++) {
        int idx = tid + it * 256;
        int r = idx >> 3, cc = idx & 7;
        int c = cc >> 2, c4 = cc & 3;
        uint32_t so = c * FA_KCH + r * 80 + c4 * 16;
        size_t go = (size_t)(bh * 64 + r) * 1024 + kb + c * 32 + c4 * 8;
        CP16(stV + so, g_vth + go);
    }
}

__global__ __launch_bounds__(256, 1) void k_flash(const int* __restrict__ mask,
                                                  float* __restrict__ out) {
    extern __shared__ char dynsmem[];
    __shared__ int msk[1024];
    uint32_t sb = smem_u32(dynsmem);
    int bh = blockIdx.y, b = bh >> 4, h = bh & 15;
    int brow = blockIdx.x * 128;
    int tid = threadIdx.x, wid = tid >> 5, lane = tid & 31;
    int wm = wid * 16;
    int g = lane >> 2, t = lane & 3;
    int rsel = lane & 15;
    uint32_t csel = ((lane >> 4) << 3);

#pragma unroll
    for (int it = 0; it < 8; it++) {
        int idx = tid + it * 256;
        int r = idx >> 4, cc = idx & 15;
        uint32_t so = (cc >> 2) * FA_ACH + r * 80 + (cc & 3) * 16;
        if (cc < 8) {
            size_t go = (size_t)(b * 1024 + brow + r) * 1024 + h * 64
                      + (cc >> 2) * 32 + (cc & 3) * 8;
            CP16(sb + so, g_uh + go);
            CP16(sb + FA_ALO + so, g_ul + go);
        } else {
            size_t go = ((size_t)bh * 1024 + brow + r) * 64
                      + ((cc >> 2) - 2) * 32 + (cc & 3) * 8;
            CP16(sb + so, g_Ath + go);
            CP16(sb + FA_ALO + so, g_Atl + go);
        }
    }
    fa_load_kv(sb, bh, b, h, 0, 0, tid);
    CP_COMMIT();
    for (int i = tid; i < 1024; i += 256) msk[i] = mask[b * 1024 + i];

    float oacc[8][4] = {};
    float m0 = -CUDART_INF_F, m1 = -CUDART_INF_F, l0 = 0.0f, l1 = 0.0f;

    const int NT = 16;
    for (int kt = 0; kt < NT; kt++) {
        CP_WAIT(0);
        __syncthreads();
        if (kt + 1 < NT) {
            fa_load_kv(sb, bh, b, h, (kt + 1) * 64, (kt + 1) & 1, tid);
            CP_COMMIT();
        }

        uint32_t Ks = sb + FA_KBASE + (kt & 1) * FA_STAGE;
        float sacc[8][4] = {};
#pragma unroll
        for (int ks = 0; ks < 8; ks++) {
            int c = ks >> 1;
            uint32_t colB = (((ks & 1) * 16) + csel) * 2;
            uint32_t ah[4], al[4], bhf[4][4], blf[4][4];
            uint32_t ad = sb + (uint32_t)(c * FA_ACH) + (uint32_t)((wm + rsel) * 80) + colB;
            ldsm4(ah, ad);
            ldsm4(al, ad + FA_ALO);
#pragma unroll
            for (int p = 0; p < 4; p++) {
                uint32_t kd = Ks + (uint32_t)(c * FA_KCH) + (uint32_t)((p * 16 + rsel) * 80) + colB;
                ldsm4(bhf[p], kd);
                ldsm4(blf[p], kd + FA_KLO);
            }
#pragma unroll
            for (int ni = 0; ni < 8; ni++) {
                int p = ni >> 1, o = ni & 1;
                uint32_t bq[2]  = { bhf[p][o], bhf[p][o + 2] };
                uint32_t bql[2] = { blf[p][o], blf[p][o + 2] };
                mma_f16(sacc[ni], ah, bq);
                mma_f16(sacc[ni], ah, bql);
                mma_f16(sacc[ni], al, bq);
            }
        }

        int kb = kt * 64;
        float tmax0 = -CUDART_INF_F, tmax1 = -CUDART_INF_F;
#pragma unroll
        for (int ni = 0; ni < 8; ni++) {
            int kc = kb + ni * 8 + 2 * t;
            if (msk[kc] == 0)     { sacc[ni][0] = -CUDART_INF_F; sacc[ni][2] = -CUDART_INF_F; }
            if (msk[kc + 1] == 0) { sacc[ni][1] = -CUDART_INF_F; sacc[ni][3] = -CUDART_INF_F; }
            tmax0 = fmaxf(tmax0, fmaxf(sacc[ni][0], sacc[ni][1]));
            tmax1 = fmaxf(tmax1, fmaxf(sacc[ni][2], sacc[ni][3]));
        }
        tmax0 = fmaxf(tmax0, __shfl_xor_sync(0xffffffffu, tmax0, 1));
        tmax0 = fmaxf(tmax0, __shfl_xor_sync(0xffffffffu, tmax0, 2));
        tmax1 = fmaxf(tmax1, __shfl_xor_sync(0xffffffffu, tmax1, 1));
        tmax1 = fmaxf(tmax1, __shfl_xor_sync(0xffffffffu, tmax1, 2));
        float nm0 = fmaxf(m0, tmax0), nm1 = fmaxf(m1, tmax1);
        float sc0 = __expf(m0 - nm0), sc1 = __expf(m1 - nm1);
        m0 = nm0; m1 = nm1;

        float rs0 = 0.0f, rs1 = 0.0f;
        uint32_t aPh[4][4];
#pragma unroll
        for (int ni = 0; ni < 8; ni++) {
            float p0 = __expf(sacc[ni][0] - nm0);
            float p1 = __expf(sacc[ni][1] - nm0);
            float p2 = __expf(sacc[ni][2] - nm1);
            float p3 = __expf(sacc[ni][3] - nm1);
            rs0 += p0 + p1;
            rs1 += p2 + p3;
            int c2 = ni >> 1, o = ni & 1;
            aPh[c2][o * 2 + 0] = packh2(p0, p1);
            aPh[c2][o * 2 + 1] = packh2(p2, p3);
        }
        rs0 += __shfl_xor_sync(0xffffffffu, rs0, 1);
        rs0 += __shfl_xor_sync(0xffffffffu, rs0, 2);
        rs1 += __shfl_xor_sync(0xffffffffu, rs1, 1);
        rs1 += __shfl_xor_sync(0xffffffffu, rs1, 2);
        l0 = l0 * sc0 + rs0;
        l1 = l1 * sc1 + rs1;
#pragma unroll
        for (int ni2 = 0; ni2 < 8; ni2++) {
            oacc[ni2][0] *= sc0; oacc[ni2][1] *= sc0;
            oacc[ni2][2] *= sc1; oacc[ni2][3] *= sc1;
        }

        uint32_t Vs = Ks + FA_VOFF;
#pragma unroll
        for (int c2 = 0; c2 < 4; c2++) {
            int c = c2 >> 1;
            uint32_t colB = (((c2 & 1) * 16) + csel) * 2;
            uint32_t bvh[4][4];
#pragma unroll
            for (int p = 0; p < 4; p++) {
                uint32_t vd = Vs + (uint32_t)(c * FA_KCH) + (uint32_t)((p * 16 + rsel) * 80) + colB;
                ldsm4(bvh[p], vd);
            }
#pragma unroll
            for (int ni2 = 0; ni2 < 8; ni2++) {
                int p = ni2 >> 1, o = ni2 & 1;
                uint32_t bq[2] = { bvh[p][o], bvh[p][o + 2] };
                mma_f16(oacc[ni2], aPh[c2], bq);
            }
        }
    }

    float inv0 = 1.0f / l0, inv1 = 1.0f / l1;
    int row0 = b * 1024 + brow + wm + g;
    int row1 = row0 + 8;
#pragma unroll
    for (int ni2 = 0; ni2 < 8; ni2++) {
        int cn = h * 64 + ni2 * 8 + 2 * t;
        *(float2*)&out[(size_t)row0 * 1024 + cn] =
            make_float2(oacc[ni2][0] * inv0, oacc[ni2][1] * inv0);
        *(float2*)&out[(size_t)row1 * 1024 + cn] =
            make_float2(oacc[ni2][2] * inv1, oacc[ni2][3] * inv1);
    }
}

// ---------------------------------------------------------------------------
extern "C" void kernel_launch(void* const* d_in, const int* in_sizes, int n_in,
                              void* d_out, int out_size) {
    (void)in_sizes; (void)n_in; (void)out_size;
    const float* x    = (const float*)d_in[0];
    const float* Wqv  = (const float*)d_in[1];
    const float* rr   = (const float*)d_in[2];
    const float* rw   = (const float*)d_in[3];
    const int*   mask = (const int*)d_in[4];
    float* out = (float*)d_out;

    cudaFuncSetAttribute(k_qv_mma, cudaFuncAttributeMaxDynamicSharedMemorySize, QV_SMEM);
    cudaFuncSetAttribute(k_flash,  cudaFuncAttributeMaxDynamicSharedMemorySize, FA_SMEM);

    k_trig<<<1024, 32>>>();
    k_decomp<<<16384 + 8192, 256>>>(x, Wqv);
    k_qv_mma<<<dim3(32, 32), 256, QV_SMEM>>>(rr);
    k_prep2<<<1024 + 256, 256>>>(rr, rw);
    k_flash<<<dim3(8, 64), 256, FA_SMEM>>>(mask, out);
}

// round 14
// speedup vs baseline: 1.3521x; 1.0246x over previous
#include <cuda_runtime.h>
#include <cuda_fp16.h>
#include <math_constants.h>
#include <math.h>
#include <cstdint>

// B=4, L=1024, D=1024, H=16, HD=64.
// S[q,k] = (q+rr)·x_k + (q+rw)·pos[k-q+L] == Â[q]·K̂[k], K=128 (angle addition).
// R14: V^T written directly from qv epilogue (vt kernel + g_v deleted).

// ---------------------------------------------------------------------------
// Device scratch
// ---------------------------------------------------------------------------
__device__ __align__(16) __half g_xh[4096 * 1024];
__device__ __align__(16) __half g_xl[4096 * 1024];
__device__ __align__(16) __half g_wh[2048 * 1024];      // Wqv^T hi [n][k]
__device__ __align__(16) __half g_wl[2048 * 1024];
__device__ __align__(16) __half g_uh[4096 * 1024];      // u = q + rr, fp16 hi
__device__ __align__(16) __half g_ul[4096 * 1024];      // u lo
__device__ __align__(16) __half g_vth[64 * 64 * 1024];  // V^T fp16 [bh*64+d][tok]
__device__ __align__(16) float g_trig[1024 * 64];       // fp32 [p][i]=sin, [p][32+i]=cos
__device__ __align__(16) __half g_tgh[1024 * 64];       // fp16 hi of trig
__device__ __align__(16) __half g_tgl[1024 * 64];       // fp16 lo of trig
__device__ __align__(16) __half g_Ath[(size_t)64 * 1024 * 64];  // Â trig half hi
__device__ __align__(16) __half g_Atl[(size_t)64 * 1024 * 64];  // Â trig half lo

// ---------------------------------------------------------------------------
// helpers
// ---------------------------------------------------------------------------
__device__ __forceinline__ uint32_t smem_u32(const void* p) {
    uint32_t a;
    asm("{ .reg .u64 t; cvta.to.shared.u64 t, %1; cvt.u32.u64 %0, t; }" : "=r"(a) : "l"(p));
    return a;
}
__device__ __forceinline__ void mma_f16(float* c, const uint32_t* a, const uint32_t* b) {
    asm volatile(
        "mma.sync.aligned.m16n8k16.row.col.f32.f16.f16.f32 "
        "{%0,%1,%2,%3}, {%4,%5,%6,%7}, {%8,%9}, {%0,%1,%2,%3};"
        : "+f"(c[0]), "+f"(c[1]), "+f"(c[2]), "+f"(c[3])
        : "r"(a[0]), "r"(a[1]), "r"(a[2]), "r"(a[3]), "r"(b[0]), "r"(b[1]));
}
__device__ __forceinline__ void ldsm4(uint32_t* r, uint32_t addr) {
    asm volatile("ldmatrix.sync.aligned.m8n8.x4.shared.b16 {%0,%1,%2,%3}, [%4];"
        : "=r"(r[0]), "=r"(r[1]), "=r"(r[2]), "=r"(r[3]) : "r"(addr));
}
__device__ __forceinline__ uint32_t packh2(float e0, float e1) {
    __half2 h = __floats2half2_rn(e0, e1);
    return *(uint32_t*)&h;
}
#define CP16(saddr, gptr) \
    asm volatile("cp.async.ca.shared.global [%0], [%1], 16;" \
        :: "r"(saddr), "l"(__cvta_generic_to_global(gptr)))
#define CP_COMMIT() asm volatile("cp.async.commit_group;")
#define CP_WAIT(n)  asm volatile("cp.async.wait_group %0;" :: "n"(n))

// ---------------------------------------------------------------------------
// K0: trig tables (fp32 + fp16 hi/lo).
// ---------------------------------------------------------------------------
__global__ void k_trig() {
    int p = blockIdx.x, i = threadIdx.x;
    double f = exp(-(double)i * (log(10000.0) / 31.0));
    double ang = (double)p * f;
    float s = (float)sin(ang), c = (float)cos(ang);
    g_trig[p * 64 + i] = s;
    g_trig[p * 64 + 32 + i] = c;
    __half sh = __float2half_rn(s), ch = __float2half_rn(c);
    g_tgh[p * 64 + i] = sh;
    g_tgh[p * 64 + 32 + i] = ch;
    g_tgl[p * 64 + i] = __float2half_rn(s - __half2float(sh));
    g_tgl[p * 64 + 32 + i] = __float2half_rn(c - __half2float(ch));
}

// ---------------------------------------------------------------------------
// K1 (fused): hi/lo fp16 decomposition of x (blocks < 16384) and Wqv^T.
// ---------------------------------------------------------------------------
__global__ __launch_bounds__(256) void k_decomp(const float* __restrict__ x,
                                                const float* __restrict__ W) {
    int bid = blockIdx.x;
    if (bid < 16384) {
        int idx = bid * 256 + threadIdx.x;
        float f = x[idx];
        __half h = __float2half_rn(f);
        g_xh[idx] = h;
        g_xl[idx] = __float2half_rn(f - __half2float(h));
    } else {
        int idx = (bid - 16384) * 256 + threadIdx.x;
        int k = idx >> 11, n = idx & 2047;
        float f = W[idx];
        __half h = __float2half_rn(f);
        g_wh[n * 1024 + k] = h;
        g_wl[n * 1024 + k] = __float2half_rn(f - __half2float(h));
    }
}

// ---------------------------------------------------------------------------
// K2: qv = x @ Wqv. q-half 3-product, v-half 1-product (xh·Wh).
// Epilogue: q -> uh/ul fp16 split; v -> g_vth fp16 TRANSPOSED (direct).
// ---------------------------------------------------------------------------
#define STAGE_BYTES 30720
#define QV_SMEM (2 * STAGE_BYTES)

__device__ __forceinline__ void stage_load(
    uint32_t sb, const __half* Ah, const __half* Al,
    const __half* Bh, const __half* Bl,
    size_t aRow, size_t bRow, int lda, int k0, int tid, bool lo)
{
#pragma unroll
    for (int it = 0; it < 2; it++) {
        int idx = tid + it * 256;
        int r = idx >> 2, c = idx & 3;
        uint32_t so = r * 80 + c * 16;
        size_t go = (aRow + r) * (size_t)lda + k0 + c * 8;
        CP16(sb + so, Ah + go);
        if (lo) CP16(sb + 10240 + so, Al + go);
    }
    {
        int r = tid >> 2, c = tid & 3;
        uint32_t so = r * 80 + c * 16;
        size_t go = (bRow + r) * (size_t)lda + k0 + c * 8;
        CP16(sb + 20480 + so, Bh + go);
        if (lo) CP16(sb + 25600 + so, Bl + go);
    }
}
__device__ __forceinline__ void stage_mma(uint32_t sb, int wm, int wn, int lane,
                                          float acc[2][4][4], bool three)
{
    int rsel = lane & 15;
    uint32_t csel = ((lane >> 4) << 3);
#pragma unroll
    for (int kc = 0; kc < 32; kc += 16) {
        uint32_t colB = (kc + csel) * 2;
        uint32_t ah[2][4], al[2][4], bhf[2][4], blf[2][4];
#pragma unroll
        for (int mi = 0; mi < 2; mi++) {
            uint32_t ad = sb + (uint32_t)((wm + mi * 16 + rsel) * 80) + colB;
            ldsm4(ah[mi], ad);
            if (three) ldsm4(al[mi], ad + 10240);
        }
#pragma unroll
        for (int p = 0; p < 2; p++) {
            uint32_t bd = sb + 20480 + (uint32_t)((wn + p * 16 + rsel) * 80) + colB;
            ldsm4(bhf[p], bd);
            if (three) ldsm4(blf[p], bd + 5120);
        }
#pragma unroll
        for (int mi = 0; mi < 2; mi++)
#pragma unroll
            for (int ni = 0; ni < 4; ni++) {
                int p = ni >> 1, o = ni & 1;
                uint32_t bq[2] = { bhf[p][o], bhf[p][o + 2] };
                mma_f16(acc[mi][ni], ah[mi], bq);
                if (three) {
                    uint32_t bql[2] = { blf[p][o], blf[p][o + 2] };
                    mma_f16(acc[mi][ni], ah[mi], bql);
                    mma_f16(acc[mi][ni], al[mi], bq);
                }
            }
    }
}

__global__ __launch_bounds__(256, 2) void k_qv_mma(const float* __restrict__ rr) {
    extern __shared__ char dynsmem[];
    uint32_t sbase = smem_u32(dynsmem);
    int tid = threadIdx.x, wid = tid >> 5, lane = tid & 31;
    int wm = (wid >> 1) * 32, wn = (wid & 1) * 32;
    int g = lane >> 2, t = lane & 3;
    int brow = blockIdx.y * 128, bcol = blockIdx.x * 64;
    bool is_q = (bcol < 1024);

    float acc[2][4][4] = {};
    const int NS = 32;
    stage_load(sbase, g_xh, g_xl, g_wh, g_wl, brow, bcol, 1024, 0, tid, is_q);
    CP_COMMIT();
    for (int s = 0; s < NS; s++) {
        CP_WAIT(0);
        __syncthreads();
        if (s + 1 < NS) {
            stage_load(sbase + ((s + 1) & 1) * STAGE_BYTES, g_xh, g_xl, g_wh, g_wl,
                       brow, bcol, 1024, (s + 1) * 32, tid, is_q);
            CP_COMMIT();
        }
        stage_mma(sbase + (s & 1) * STAGE_BYTES, wm, wn, lane, acc, is_q);
    }

#pragma unroll
    for (int mi = 0; mi < 2; mi++)
#pragma unroll
        for (int ni = 0; ni < 4; ni++) {
            int row0 = brow + wm + mi * 16 + g;
            int cn = bcol + wn + ni * 8 + 2 * t;
            float2 v0 = make_float2(acc[mi][ni][0], acc[mi][ni][1]);
            float2 v1 = make_float2(acc[mi][ni][2], acc[mi][ni][3]);
            if (is_q) {
                float2 rb = *(const float2*)(rr + cn);
                v0.x += rb.x; v0.y += rb.y;
                v1.x += rb.x; v1.y += rb.y;
                __half2 h0 = __floats2half2_rn(v0.x, v0.y);
                __half2 l0 = __floats2half2_rn(v0.x - __half2float(h0.x),
                                               v0.y - __half2float(h0.y));
                __half2 h1 = __floats2half2_rn(v1.x, v1.y);
                __half2 l1 = __floats2half2_rn(v1.x - __half2float(h1.x),
                                               v1.y - __half2float(h1.y));
                *(__half2*)&g_uh[(size_t)row0 * 1024 + cn] = h0;
                *(__half2*)&g_ul[(size_t)row0 * 1024 + cn] = l0;
                *(__half2*)&g_uh[(size_t)(row0 + 8) * 1024 + cn] = h1;
                *(__half2*)&g_ul[(size_t)(row0 + 8) * 1024 + cn] = l1;
            } else {
                // direct transposed V^T write: g_vth[(bh*64+d)*1024 + tok]
                int vc = cn - 1024;             // global v col, 0..1023
                int h2 = vc >> 6, d = vc & 63;  // head, in-head dim (d, d+1)
                int b2 = row0 >> 10, tok = row0 & 1023;
                size_t base = ((size_t)((b2 << 4) + h2) * 64 + d) * 1024 + tok;
                g_vth[base]            = __float2half_rn(v0.x);
                g_vth[base + 1024]     = __float2half_rn(v0.y);   // d+1
                g_vth[base + 8]        = __float2half_rn(v1.x);   // tok+8
                g_vth[base + 1024 + 8] = __float2half_rn(v1.y);
            }
        }
}

// ---------------------------------------------------------------------------
// K3: build Â trig half (fp16 hi/lo). w = u - rr + rw, u = uh + ul (exact).
// ---------------------------------------------------------------------------
__global__ __launch_bounds__(256) void k_build_A(const float* __restrict__ rr,
                                                 const float* __restrict__ rw) {
    int idx = blockIdx.x * 256 + threadIdx.x;     // bh*1024 + q
    int bh = idx >> 10, q = idx & 1023;
    int b = bh >> 4, h = bh & 15;
    const __half* uhp = g_uh + (size_t)(b * 1024 + q) * 1024 + h * 64;
    const __half* ulp = g_ul + (size_t)(b * 1024 + q) * 1024 + h * 64;
    __half* ah = g_Ath + (size_t)idx * 64;
    __half* al = g_Atl + (size_t)idx * 64;
    const float* tg = g_trig + q * 64;
#pragma unroll 8
    for (int i = 0; i < 32; i++) {
        float u0 = __half2float(uhp[i]) + __half2float(ulp[i]);
        float u1 = __half2float(uhp[32 + i]) + __half2float(ulp[32 + i]);
        float w0 = u0 - rr[h * 64 + i] + rw[h * 64 + i];
        float w1 = u1 - rr[h * 64 + 32 + i] + rw[h * 64 + 32 + i];
        float sq = tg[i], cq = tg[32 + i];
        float a1 = w0 * cq + w1 * sq;
        float a2 = w1 * cq - w0 * sq;
        __half hh1 = __float2half_rn(a1);
        ah[i] = hh1; al[i] = __float2half_rn(a1 - __half2float(hh1));
        __half hh2 = __float2half_rn(a2);
        ah[32 + i] = hh2; al[32 + i] = __float2half_rn(a2 - __half2float(hh2));
    }
}

// ---------------------------------------------------------------------------
// K5: flash attention (unchanged from R12/R13).
// ---------------------------------------------------------------------------
#define FA_ACH 10240
#define FA_ALO 40960
#define FA_KBASE 81920
#define FA_KCH 5120
#define FA_KLO 20480
#define FA_VOFF 40960
#define FA_STAGE 51200
#define FA_SMEM (FA_KBASE + 2 * FA_STAGE)   // 184320

__device__ __forceinline__ void fa_load_kv(uint32_t sb, int bh, int b, int h,
                                           int kb, int buf, int tid) {
    uint32_t st = sb + FA_KBASE + buf * FA_STAGE;
#pragma unroll
    for (int it = 0; it < 4; it++) {
        int idx = tid + it * 256;
        int r = idx >> 4, cc = idx & 15;
        uint32_t so = (cc >> 2) * FA_KCH + r * 80 + (cc & 3) * 16;
        if (cc < 8) {
            size_t go = (size_t)(b * 1024 + kb + r) * 1024 + h * 64
                      + (cc >> 2) * 32 + (cc & 3) * 8;
            CP16(st + so, g_xh + go);
            CP16(st + FA_KLO + so, g_xl + go);
        } else {
            size_t go = (size_t)(kb + r) * 64 + ((cc >> 2) - 2) * 32 + (cc & 3) * 8;
            CP16(st + so, g_tgh + go);
            CP16(st + FA_KLO + so, g_tgl + go);
        }
    }
    uint32_t stV = st + FA_VOFF;
#pragma unroll
    for (int it = 0; it < 2; it++) {
        int idx = tid + it * 256;
        int r = idx >> 3, cc = idx & 7;
        int c = cc >> 2, c4 = cc & 3;
        uint32_t so = c * FA_KCH + r * 80 + c4 * 16;
        size_t go = (size_t)(bh * 64 + r) * 1024 + kb + c * 32 + c4 * 8;
        CP16(stV + so, g_vth + go);
    }
}

__global__ __launch_bounds__(256, 1) void k_flash(const int* __restrict__ mask,
                                                  float* __restrict__ out) {
    extern __shared__ char dynsmem[];
    __shared__ int msk[1024];
    uint32_t sb = smem_u32(dynsmem);
    int bh = blockIdx.y, b = bh >> 4, h = bh & 15;
    int brow = blockIdx.x * 128;
    int tid = threadIdx.x, wid = tid >> 5, lane = tid & 31;
    int wm = wid * 16;
    int g = lane >> 2, t = lane & 3;
    int rsel = lane & 15;
    uint32_t csel = ((lane >> 4) << 3);

#pragma unroll
    for (int it = 0; it < 8; it++) {
        int idx = tid + it * 256;
        int r = idx >> 4, cc = idx & 15;
        uint32_t so = (cc >> 2) * FA_ACH + r * 80 + (cc & 3) * 16;
        if (cc < 8) {
            size_t go = (size_t)(b * 1024 + brow + r) * 1024 + h * 64
                      + (cc >> 2) * 32 + (cc & 3) * 8;
            CP16(sb + so, g_uh + go);
            CP16(sb + FA_ALO + so, g_ul + go);
        } else {
            size_t go = ((size_t)bh * 1024 + brow + r) * 64
                      + ((cc >> 2) - 2) * 32 + (cc & 3) * 8;
            CP16(sb + so, g_Ath + go);
            CP16(sb + FA_ALO + so, g_Atl + go);
        }
    }
    fa_load_kv(sb, bh, b, h, 0, 0, tid);
    CP_COMMIT();
    for (int i = tid; i < 1024; i += 256) msk[i] = mask[b * 1024 + i];

    float oacc[8][4] = {};
    float m0 = -CUDART_INF_F, m1 = -CUDART_INF_F, l0 = 0.0f, l1 = 0.0f;

    const int NT = 16;
    for (int kt = 0; kt < NT; kt++) {
        CP_WAIT(0);
        __syncthreads();
        if (kt + 1 < NT) {
            fa_load_kv(sb, bh, b, h, (kt + 1) * 64, (kt + 1) & 1, tid);
            CP_COMMIT();
        }

        uint32_t Ks = sb + FA_KBASE + (kt & 1) * FA_STAGE;
        float sacc[8][4] = {};
#pragma unroll
        for (int ks = 0; ks < 8; ks++) {
            int c = ks >> 1;
            uint32_t colB = (((ks & 1) * 16) + csel) * 2;
            uint32_t ah[4], al[4], bhf[4][4], blf[4][4];
            uint32_t ad = sb + (uint32_t)(c * FA_ACH) + (uint32_t)((wm + rsel) * 80) + colB;
            ldsm4(ah, ad);
            ldsm4(al, ad + FA_ALO);
#pragma unroll
            for (int p = 0; p < 4; p++) {
                uint32_t kd = Ks + (uint32_t)(c * FA_KCH) + (uint32_t)((p * 16 + rsel) * 80) + colB;
                ldsm4(bhf[p], kd);
                ldsm4(blf[p], kd + FA_KLO);
            }
#pragma unroll
            for (int ni = 0; ni < 8; ni++) {
                int p = ni >> 1, o = ni & 1;
                uint32_t bq[2]  = { bhf[p][o], bhf[p][o + 2] };
                uint32_t bql[2] = { blf[p][o], blf[p][o + 2] };
                mma_f16(sacc[ni], ah, bq);
                mma_f16(sacc[ni], ah, bql);
                mma_f16(sacc[ni], al, bq);
            }
        }

        int kb = kt * 64;
        float tmax0 = -CUDART_INF_F, tmax1 = -CUDART_INF_F;
#pragma unroll
        for (int ni = 0; ni < 8; ni++) {
            int kc = kb + ni * 8 + 2 * t;
            if (msk[kc] == 0)     { sacc[ni][0] = -CUDART_INF_F; sacc[ni][2] = -CUDART_INF_F; }
            if (msk[kc + 1] == 0) { sacc[ni][1] = -CUDART_INF_F; sacc[ni][3] = -CUDART_INF_F; }
            tmax0 = fmaxf(tmax0, fmaxf(sacc[ni][0], sacc[ni][1]));
            tmax1 = fmaxf(tmax1, fmaxf(sacc[ni][2], sacc[ni][3]));
        }
        tmax0 = fmaxf(tmax0, __shfl_xor_sync(0xffffffffu, tmax0, 1));
        tmax0 = fmaxf(tmax0, __shfl_xor_sync(0xffffffffu, tmax0, 2));
        tmax1 = fmaxf(tmax1, __shfl_xor_sync(0xffffffffu, tmax1, 1));
        tmax1 = fmaxf(tmax1, __shfl_xor_sync(0xffffffffu, tmax1, 2));
        float nm0 = fmaxf(m0, tmax0), nm1 = fmaxf(m1, tmax1);
        float sc0 = __expf(m0 - nm0), sc1 = __expf(m1 - nm1);
        m0 = nm0; m1 = nm1;

        float rs0 = 0.0f, rs1 = 0.0f;
        uint32_t aPh[4][4];
#pragma unroll
        for (int ni = 0; ni < 8; ni++) {
            float p0 = __expf(sacc[ni][0] - nm0);
            float p1 = __expf(sacc[ni][1] - nm0);
            float p2 = __expf(sacc[ni][2] - nm1);
            float p3 = __expf(sacc[ni][3] - nm1);
            rs0 += p0 + p1;
            rs1 += p2 + p3;
            int c2 = ni >> 1, o = ni & 1;
            aPh[c2][o * 2 + 0] = packh2(p0, p1);
            aPh[c2][o * 2 + 1] = packh2(p2, p3);
        }
        rs0 += __shfl_xor_sync(0xffffffffu, rs0, 1);
        rs0 += __shfl_xor_sync(0xffffffffu, rs0, 2);
        rs1 += __shfl_xor_sync(0xffffffffu, rs1, 1);
        rs1 += __shfl_xor_sync(0xffffffffu, rs1, 2);
        l0 = l0 * sc0 + rs0;
        l1 = l1 * sc1 + rs1;
#pragma unroll
        for (int ni2 = 0; ni2 < 8; ni2++) {
            oacc[ni2][0] *= sc0; oacc[ni2][1] *= sc0;
            oacc[ni2][2] *= sc1; oacc[ni2][3] *= sc1;
        }

        uint32_t Vs = Ks + FA_VOFF;
#pragma unroll
        for (int c2 = 0; c2 < 4; c2++) {
            int c = c2 >> 1;
            uint32_t colB = (((c2 & 1) * 16) + csel) * 2;
            uint32_t bvh[4][4];
#pragma unroll
            for (int p = 0; p < 4; p++) {
                uint32_t vd = Vs + (uint32_t)(c * FA_KCH) + (uint32_t)((p * 16 + rsel) * 80) + colB;
                ldsm4(bvh[p], vd);
            }
#pragma unroll
            for (int ni2 = 0; ni2 < 8; ni2++) {
                int p = ni2 >> 1, o = ni2 & 1;
                uint32_t bq[2] = { bvh[p][o], bvh[p][o + 2] };
                mma_f16(oacc[ni2], aPh[c2], bq);
            }
        }
    }

    float inv0 = 1.0f / l0, inv1 = 1.0f / l1;
    int row0 = b * 1024 + brow + wm + g;
    int row1 = row0 + 8;
#pragma unroll
    for (int ni2 = 0; ni2 < 8; ni2++) {
        int cn = h * 64 + ni2 * 8 + 2 * t;
        *(float2*)&out[(size_t)row0 * 1024 + cn] =
            make_float2(oacc[ni2][0] * inv0, oacc[ni2][1] * inv0);
        *(float2*)&out[(size_t)row1 * 1024 + cn] =
            make_float2(oacc[ni2][2] * inv1, oacc[ni2][3] * inv1);
    }
}

// ---------------------------------------------------------------------------
extern "C" void kernel_launch(void* const* d_in, const int* in_sizes, int n_in,
                              void* d_out, int out_size) {
    (void)in_sizes; (void)n_in; (void)out_size;
    const float* x    = (const float*)d_in[0];
    const float* Wqv  = (const float*)d_in[1];
    const float* rr   = (const float*)d_in[2];
    const float* rw   = (const float*)d_in[3];
    const int*   mask = (const int*)d_in[4];
    float* out = (float*)d_out;

    cudaFuncSetAttribute(k_qv_mma, cudaFuncAttributeMaxDynamicSharedMemorySize, QV_SMEM);
    cudaFuncSetAttribute(k_flash,  cudaFuncAttributeMaxDynamicSharedMemorySize, FA_SMEM);

    k_trig<<<1024, 32>>>();
    k_decomp<<<16384 + 8192, 256>>>(x, Wqv);
    k_qv_mma<<<dim3(32, 32), 256, QV_SMEM>>>(rr);
    k_build_A<<<256, 256>>>(rr, rw);
    k_flash<<<dim3(8, 64), 256, FA_SMEM>>>(mask, out);
}

// round 15
// speedup vs baseline: 1.4795x; 1.0942x over previous
#include <cuda_runtime.h>
#include <cuda_fp16.h>
#include <math_constants.h>
#include <math.h>
#include <cstdint>

// B=4, L=1024, D=1024, H=16, HD=64.
// S[q,k] = (q+rr)·x_k + (q+rw)·pos[k-q+L] == Â[q]·K̂[k], K=128 (angle addition).
// R15: coalesced build_A (warp-per-row) + smem-transposed W decomp.

// ---------------------------------------------------------------------------
// Device scratch
// ---------------------------------------------------------------------------
__device__ __align__(16) __half g_xh[4096 * 1024];
__device__ __align__(16) __half g_xl[4096 * 1024];
__device__ __align__(16) __half g_wh[2048 * 1024];      // Wqv^T hi [n][k]
__device__ __align__(16) __half g_wl[2048 * 1024];
__device__ __align__(16) __half g_uh[4096 * 1024];      // u = q + rr, fp16 hi
__device__ __align__(16) __half g_ul[4096 * 1024];      // u lo
__device__ __align__(16) __half g_vth[64 * 64 * 1024];  // V^T fp16 [bh*64+d][tok]
__device__ __align__(16) float g_trig[1024 * 64];       // fp32 [p][i]=sin, [p][32+i]=cos
__device__ __align__(16) __half g_tgh[1024 * 64];       // fp16 hi of trig
__device__ __align__(16) __half g_tgl[1024 * 64];       // fp16 lo of trig
__device__ __align__(16) __half g_Ath[(size_t)64 * 1024 * 64];  // Â trig half hi
__device__ __align__(16) __half g_Atl[(size_t)64 * 1024 * 64];  // Â trig half lo

// ---------------------------------------------------------------------------
// helpers
// ---------------------------------------------------------------------------
__device__ __forceinline__ uint32_t smem_u32(const void* p) {
    uint32_t a;
    asm("{ .reg .u64 t; cvta.to.shared.u64 t, %1; cvt.u32.u64 %0, t; }" : "=r"(a) : "l"(p));
    return a;
}
__device__ __forceinline__ void mma_f16(float* c, const uint32_t* a, const uint32_t* b) {
    asm volatile(
        "mma.sync.aligned.m16n8k16.row.col.f32.f16.f16.f32 "
        "{%0,%1,%2,%3}, {%4,%5,%6,%7}, {%8,%9}, {%0,%1,%2,%3};"
        : "+f"(c[0]), "+f"(c[1]), "+f"(c[2]), "+f"(c[3])
        : "r"(a[0]), "r"(a[1]), "r"(a[2]), "r"(a[3]), "r"(b[0]), "r"(b[1]));
}
__device__ __forceinline__ void ldsm4(uint32_t* r, uint32_t addr) {
    asm volatile("ldmatrix.sync.aligned.m8n8.x4.shared.b16 {%0,%1,%2,%3}, [%4];"
        : "=r"(r[0]), "=r"(r[1]), "=r"(r[2]), "=r"(r[3]) : "r"(addr));
}
__device__ __forceinline__ uint32_t packh2(float e0, float e1) {
    __half2 h = __floats2half2_rn(e0, e1);
    return *(uint32_t*)&h;
}
#define CP16(saddr, gptr) \
    asm volatile("cp.async.ca.shared.global [%0], [%1], 16;" \
        :: "r"(saddr), "l"(__cvta_generic_to_global(gptr)))
#define CP_COMMIT() asm volatile("cp.async.commit_group;")
#define CP_WAIT(n)  asm volatile("cp.async.wait_group %0;" :: "n"(n))

// ---------------------------------------------------------------------------
// K0: trig tables (fp32 + fp16 hi/lo).
// ---------------------------------------------------------------------------
__global__ void k_trig() {
    int p = blockIdx.x, i = threadIdx.x;
    double f = exp(-(double)i * (log(10000.0) / 31.0));
    double ang = (double)p * f;
    float s = (float)sin(ang), c = (float)cos(ang);
    g_trig[p * 64 + i] = s;
    g_trig[p * 64 + 32 + i] = c;
    __half sh = __float2half_rn(s), ch = __float2half_rn(c);
    g_tgh[p * 64 + i] = sh;
    g_tgh[p * 64 + 32 + i] = ch;
    g_tgl[p * 64 + i] = __float2half_rn(s - __half2float(sh));
    g_tgl[p * 64 + 32 + i] = __float2half_rn(c - __half2float(ch));
}

// ---------------------------------------------------------------------------
// K1 (fused): x decomposition (blocks < 16384, coalesced) and W^T via smem
// tile transpose (blocks >= 16384: 16 k-tiles x 32 n-tiles of 64x64).
// ---------------------------------------------------------------------------
__global__ __launch_bounds__(256) void k_decomp(const float* __restrict__ x,
                                                const float* __restrict__ W) {
    __shared__ float tile[64][65];
    int bid = blockIdx.x;
    if (bid < 16384) {
        int idx = bid * 256 + threadIdx.x;
        float f = x[idx];
        __half h = __float2half_rn(f);
        g_xh[idx] = h;
        g_xl[idx] = __float2half_rn(f - __half2float(h));
    } else {
        int wt = bid - 16384;                 // 0..511
        int k0 = (wt >> 5) * 64;              // 16 k-tiles
        int n0 = (wt & 31) * 64;              // 32 n-tiles
        int tid = threadIdx.x;
#pragma unroll
        for (int it = 0; it < 16; it++) {
            int idx = tid + it * 256;         // 0..4095
            int r = idx >> 6, c = idx & 63;   // r = k, c = n
            tile[r][c] = W[(size_t)(k0 + r) * 2048 + n0 + c];
        }
        __syncthreads();
#pragma unroll
        for (int it = 0; it < 16; it++) {
            int idx = tid + it * 256;
            int r = idx >> 6, c = idx & 63;   // r = n, c = k
            float f = tile[c][r];
            __half h = __float2half_rn(f);
            size_t o = (size_t)(n0 + r) * 1024 + k0 + c;
            g_wh[o] = h;
            g_wl[o] = __float2half_rn(f - __half2float(h));
        }
    }
}

// ---------------------------------------------------------------------------
// K2: qv = x @ Wqv. q-half 3-product, v-half 1-product (xh·Wh).
// Epilogue: q -> uh/ul fp16 split; v -> g_vth fp16 TRANSPOSED (direct).
// ---------------------------------------------------------------------------
#define STAGE_BYTES 30720
#define QV_SMEM (2 * STAGE_BYTES)

__device__ __forceinline__ void stage_load(
    uint32_t sb, const __half* Ah, const __half* Al,
    const __half* Bh, const __half* Bl,
    size_t aRow, size_t bRow, int lda, int k0, int tid, bool lo)
{
#pragma unroll
    for (int it = 0; it < 2; it++) {
        int idx = tid + it * 256;
        int r = idx >> 2, c = idx & 3;
        uint32_t so = r * 80 + c * 16;
        size_t go = (aRow + r) * (size_t)lda + k0 + c * 8;
        CP16(sb + so, Ah + go);
        if (lo) CP16(sb + 10240 + so, Al + go);
    }
    {
        int r = tid >> 2, c = tid & 3;
        uint32_t so = r * 80 + c * 16;
        size_t go = (bRow + r) * (size_t)lda + k0 + c * 8;
        CP16(sb + 20480 + so, Bh + go);
        if (lo) CP16(sb + 25600 + so, Bl + go);
    }
}
__device__ __forceinline__ void stage_mma(uint32_t sb, int wm, int wn, int lane,
                                          float acc[2][4][4], bool three)
{
    int rsel = lane & 15;
    uint32_t csel = ((lane >> 4) << 3);
#pragma unroll
    for (int kc = 0; kc < 32; kc += 16) {
        uint32_t colB = (kc + csel) * 2;
        uint32_t ah[2][4], al[2][4], bhf[2][4], blf[2][4];
#pragma unroll
        for (int mi = 0; mi < 2; mi++) {
            uint32_t ad = sb + (uint32_t)((wm + mi * 16 + rsel) * 80) + colB;
            ldsm4(ah[mi], ad);
            if (three) ldsm4(al[mi], ad + 10240);
        }
#pragma unroll
        for (int p = 0; p < 2; p++) {
            uint32_t bd = sb + 20480 + (uint32_t)((wn + p * 16 + rsel) * 80) + colB;
            ldsm4(bhf[p], bd);
            if (three) ldsm4(blf[p], bd + 5120);
        }
#pragma unroll
        for (int mi = 0; mi < 2; mi++)
#pragma unroll
            for (int ni = 0; ni < 4; ni++) {
                int p = ni >> 1, o = ni & 1;
                uint32_t bq[2] = { bhf[p][o], bhf[p][o + 2] };
                mma_f16(acc[mi][ni], ah[mi], bq);
                if (three) {
                    uint32_t bql[2] = { blf[p][o], blf[p][o + 2] };
                    mma_f16(acc[mi][ni], ah[mi], bql);
                    mma_f16(acc[mi][ni], al[mi], bq);
                }
            }
    }
}

__global__ __launch_bounds__(256, 2) void k_qv_mma(const float* __restrict__ rr) {
    extern __shared__ char dynsmem[];
    uint32_t sbase = smem_u32(dynsmem);
    int tid = threadIdx.x, wid = tid >> 5, lane = tid & 31;
    int wm = (wid >> 1) * 32, wn = (wid & 1) * 32;
    int g = lane >> 2, t = lane & 3;
    int brow = blockIdx.y * 128, bcol = blockIdx.x * 64;
    bool is_q = (bcol < 1024);

    float acc[2][4][4] = {};
    const int NS = 32;
    stage_load(sbase, g_xh, g_xl, g_wh, g_wl, brow, bcol, 1024, 0, tid, is_q);
    CP_COMMIT();
    for (int s = 0; s < NS; s++) {
        CP_WAIT(0);
        __syncthreads();
        if (s + 1 < NS) {
            stage_load(sbase + ((s + 1) & 1) * STAGE_BYTES, g_xh, g_xl, g_wh, g_wl,
                       brow, bcol, 1024, (s + 1) * 32, tid, is_q);
            CP_COMMIT();
        }
        stage_mma(sbase + (s & 1) * STAGE_BYTES, wm, wn, lane, acc, is_q);
    }

#pragma unroll
    for (int mi = 0; mi < 2; mi++)
#pragma unroll
        for (int ni = 0; ni < 4; ni++) {
            int row0 = brow + wm + mi * 16 + g;
            int cn = bcol + wn + ni * 8 + 2 * t;
            float2 v0 = make_float2(acc[mi][ni][0], acc[mi][ni][1]);
            float2 v1 = make_float2(acc[mi][ni][2], acc[mi][ni][3]);
            if (is_q) {
                float2 rb = *(const float2*)(rr + cn);
                v0.x += rb.x; v0.y += rb.y;
                v1.x += rb.x; v1.y += rb.y;
                __half2 h0 = __floats2half2_rn(v0.x, v0.y);
                __half2 l0 = __floats2half2_rn(v0.x - __half2float(h0.x),
                                               v0.y - __half2float(h0.y));
                __half2 h1 = __floats2half2_rn(v1.x, v1.y);
                __half2 l1 = __floats2half2_rn(v1.x - __half2float(h1.x),
                                               v1.y - __half2float(h1.y));
                *(__half2*)&g_uh[(size_t)row0 * 1024 + cn] = h0;
                *(__half2*)&g_ul[(size_t)row0 * 1024 + cn] = l0;
                *(__half2*)&g_uh[(size_t)(row0 + 8) * 1024 + cn] = h1;
                *(__half2*)&g_ul[(size_t)(row0 + 8) * 1024 + cn] = l1;
            } else {
                // direct transposed V^T write: g_vth[(bh*64+d)*1024 + tok]
                int vc = cn - 1024;             // global v col, 0..1023
                int h2 = vc >> 6, d = vc & 63;  // head, in-head dim (d, d+1)
                int b2 = row0 >> 10, tok = row0 & 1023;
                size_t base = ((size_t)((b2 << 4) + h2) * 64 + d) * 1024 + tok;
                g_vth[base]            = __float2half_rn(v0.x);
                g_vth[base + 1024]     = __float2half_rn(v0.y);   // d+1
                g_vth[base + 8]        = __float2half_rn(v1.x);   // tok+8
                g_vth[base + 1024 + 8] = __float2half_rn(v1.y);
            }
        }
}

// ---------------------------------------------------------------------------
// K3: build Â trig half, warp-per-row (fully coalesced).
// Row = bh*1024+q. Lane i handles dims (i, 32+i). 8 rows per 256-thr block.
// ---------------------------------------------------------------------------
__global__ __launch_bounds__(256) void k_build_A(const float* __restrict__ rr,
                                                 const float* __restrict__ rw) {
    int idx = (blockIdx.x * 256 + threadIdx.x) >> 5;   // row: bh*1024 + q
    int i = threadIdx.x & 31;                          // lane = dim
    int bh = idx >> 10, q = idx & 1023;
    int b = bh >> 4, h = bh & 15;
    const __half* uhp = g_uh + (size_t)(b * 1024 + q) * 1024 + h * 64;
    const __half* ulp = g_ul + (size_t)(b * 1024 + q) * 1024 + h * 64;
    __half* ah = g_Ath + (size_t)idx * 64;
    __half* al = g_Atl + (size_t)idx * 64;
    const float* tg = g_trig + q * 64;

    float u0 = __half2float(uhp[i]) + __half2float(ulp[i]);
    float u1 = __half2float(uhp[32 + i]) + __half2float(ulp[32 + i]);
    float w0 = u0 - rr[h * 64 + i] + rw[h * 64 + i];
    float w1 = u1 - rr[h * 64 + 32 + i] + rw[h * 64 + 32 + i];
    float sq = tg[i], cq = tg[32 + i];
    float a1 = w0 * cq + w1 * sq;
    float a2 = w1 * cq - w0 * sq;
    __half hh1 = __float2half_rn(a1);
    ah[i] = hh1; al[i] = __float2half_rn(a1 - __half2float(hh1));
    __half hh2 = __float2half_rn(a2);
    ah[32 + i] = hh2; al[32 + i] = __float2half_rn(a2 - __half2float(hh2));
}

// ---------------------------------------------------------------------------
// K5: flash attention (unchanged from R12-R14).
// ---------------------------------------------------------------------------
#define FA_ACH 10240
#define FA_ALO 40960
#define FA_KBASE 81920
#define FA_KCH 5120
#define FA_KLO 20480
#define FA_VOFF 40960
#define FA_STAGE 51200
#define FA_SMEM (FA_KBASE + 2 * FA_STAGE)   // 184320

__device__ __forceinline__ void fa_load_kv(uint32_t sb, int bh, int b, int h,
                                           int kb, int buf, int tid) {
    uint32_t st = sb + FA_KBASE + buf * FA_STAGE;
#pragma unroll
    for (int it = 0; it < 4; it++) {
        int idx = tid + it * 256;
        int r = idx >> 4, cc = idx & 15;
        uint32_t so = (cc >> 2) * FA_KCH + r * 80 + (cc & 3) * 16;
        if (cc < 8) {
            size_t go = (size_t)(b * 1024 + kb + r) * 1024 + h * 64
                      + (cc >> 2) * 32 + (cc & 3) * 8;
            CP16(st + so, g_xh + go);
            CP16(st + FA_KLO + so, g_xl + go);
        } else {
            size_t go = (size_t)(kb + r) * 64 + ((cc >> 2) - 2) * 32 + (cc & 3) * 8;
            CP16(st + so, g_tgh + go);
            CP16(st + FA_KLO + so, g_tgl + go);
        }
    }
    uint32_t stV = st + FA_VOFF;
#pragma unroll
    for (int it = 0; it < 2; it++) {
        int idx = tid + it * 256;
        int r = idx >> 3, cc = idx & 7;
        int c = cc >> 2, c4 = cc & 3;
        uint32_t so = c * FA_KCH + r * 80 + c4 * 16;
        size_t go = (size_t)(bh * 64 + r) * 1024 + kb + c * 32 + c4 * 8;
        CP16(stV + so, g_vth + go);
    }
}

__global__ __launch_bounds__(256, 1) void k_flash(const int* __restrict__ mask,
                                                  float* __restrict__ out) {
    extern __shared__ char dynsmem[];
    __shared__ int msk[1024];
    uint32_t sb = smem_u32(dynsmem);
    int bh = blockIdx.y, b = bh >> 4, h = bh & 15;
    int brow = blockIdx.x * 128;
    int tid = threadIdx.x, wid = tid >> 5, lane = tid & 31;
    int wm = wid * 16;
    int g = lane >> 2, t = lane & 3;
    int rsel = lane & 15;
    uint32_t csel = ((lane >> 4) << 3);

#pragma unroll
    for (int it = 0; it < 8; it++) {
        int idx = tid + it * 256;
        int r = idx >> 4, cc = idx & 15;
        uint32_t so = (cc >> 2) * FA_ACH + r * 80 + (cc & 3) * 16;
        if (cc < 8) {
            size_t go = (size_t)(b * 1024 + brow + r) * 1024 + h * 64
                      + (cc >> 2) * 32 + (cc & 3) * 8;
            CP16(sb + so, g_uh + go);
            CP16(sb + FA_ALO + so, g_ul + go);
        } else {
            size_t go = ((size_t)bh * 1024 + brow + r) * 64
                      + ((cc >> 2) - 2) * 32 + (cc & 3) * 8;
            CP16(sb + so, g_Ath + go);
            CP16(sb + FA_ALO + so, g_Atl + go);
        }
    }
    fa_load_kv(sb, bh, b, h, 0, 0, tid);
    CP_COMMIT();
    for (int i = tid; i < 1024; i += 256) msk[i] = mask[b * 1024 + i];

    float oacc[8][4] = {};
    float m0 = -CUDART_INF_F, m1 = -CUDART_INF_F, l0 = 0.0f, l1 = 0.0f;

    const int NT = 16;
    for (int kt = 0; kt < NT; kt++) {
        CP_WAIT(0);
        __syncthreads();
        if (kt + 1 < NT) {
            fa_load_kv(sb, bh, b, h, (kt + 1) * 64, (kt + 1) & 1, tid);
            CP_COMMIT();
        }

        uint32_t Ks = sb + FA_KBASE + (kt & 1) * FA_STAGE;
        float sacc[8][4] = {};
#pragma unroll
        for (int ks = 0; ks < 8; ks++) {
            int c = ks >> 1;
            uint32_t colB = (((ks & 1) * 16) + csel) * 2;
            uint32_t ah[4], al[4], bhf[4][4], blf[4][4];
            uint32_t ad = sb + (uint32_t)(c * FA_ACH) + (uint32_t)((wm + rsel) * 80) + colB;
            ldsm4(ah, ad);
            ldsm4(al, ad + FA_ALO);
#pragma unroll
            for (int p = 0; p < 4; p++) {
                uint32_t kd = Ks + (uint32_t)(c * FA_KCH) + (uint32_t)((p * 16 + rsel) * 80) + colB;
                ldsm4(bhf[p], kd);
                ldsm4(blf[p], kd + FA_KLO);
            }
#pragma unroll
            for (int ni = 0; ni < 8; ni++) {
                int p = ni >> 1, o = ni & 1;
                uint32_t bq[2]  = { bhf[p][o], bhf[p][o + 2] };
                uint32_t bql[2] = { blf[p][o], blf[p][o + 2] };
                mma_f16(sacc[ni], ah, bq);
                mma_f16(sacc[ni], ah, bql);
                mma_f16(sacc[ni], al, bq);
            }
        }

        int kb = kt * 64;
        float tmax0 = -CUDART_INF_F, tmax1 = -CUDART_INF_F;
#pragma unroll
        for (int ni = 0; ni < 8; ni++) {
            int kc = kb + ni * 8 + 2 * t;
            if (msk[kc] == 0)     { sacc[ni][0] = -CUDART_INF_F; sacc[ni][2] = -CUDART_INF_F; }
            if (msk[kc + 1] == 0) { sacc[ni][1] = -CUDART_INF_F; sacc[ni][3] = -CUDART_INF_F; }
            tmax0 = fmaxf(tmax0, fmaxf(sacc[ni][0], sacc[ni][1]));
            tmax1 = fmaxf(tmax1, fmaxf(sacc[ni][2], sacc[ni][3]));
        }
        tmax0 = fmaxf(tmax0, __shfl_xor_sync(0xffffffffu, tmax0, 1));
        tmax0 = fmaxf(tmax0, __shfl_xor_sync(0xffffffffu, tmax0, 2));
        tmax1 = fmaxf(tmax1, __shfl_xor_sync(0xffffffffu, tmax1, 1));
        tmax1 = fmaxf(tmax1, __shfl_xor_sync(0xffffffffu, tmax1, 2));
        float nm0 = fmaxf(m0, tmax0), nm1 = fmaxf(m1, tmax1);
        float sc0 = __expf(m0 - nm0), sc1 = __expf(m1 - nm1);
        m0 = nm0; m1 = nm1;

        float rs0 = 0.0f, rs1 = 0.0f;
        uint32_t aPh[4][4];
#pragma unroll
        for (int ni = 0; ni < 8; ni++) {
            float p0 = __expf(sacc[ni][0] - nm0);
            float p1 = __expf(sacc[ni][1] - nm0);
            float p2 = __expf(sacc[ni][2] - nm1);
            float p3 = __expf(sacc[ni][3] - nm1);
            rs0 += p0 + p1;
            rs1 += p2 + p3;
            int c2 = ni >> 1, o = ni & 1;
            aPh[c2][o * 2 + 0] = packh2(p0, p1);
            aPh[c2][o * 2 + 1] = packh2(p2, p3);
        }
        rs0 += __shfl_xor_sync(0xffffffffu, rs0, 1);
        rs0 += __shfl_xor_sync(0xffffffffu, rs0, 2);
        rs1 += __shfl_xor_sync(0xffffffffu, rs1, 1);
        rs1 += __shfl_xor_sync(0xffffffffu, rs1, 2);
        l0 = l0 * sc0 + rs0;
        l1 = l1 * sc1 + rs1;
#pragma unroll
        for (int ni2 = 0; ni2 < 8; ni2++) {
            oacc[ni2][0] *= sc0; oacc[ni2][1] *= sc0;
            oacc[ni2][2] *= sc1; oacc[ni2][3] *= sc1;
        }

        uint32_t Vs = Ks + FA_VOFF;
#pragma unroll
        for (int c2 = 0; c2 < 4; c2++) {
            int c = c2 >> 1;
            uint32_t colB = (((c2 & 1) * 16) + csel) * 2;
            uint32_t bvh[4][4];
#pragma unroll
            for (int p = 0; p < 4; p++) {
                uint32_t vd = Vs + (uint32_t)(c * FA_KCH) + (uint32_t)((p * 16 + rsel) * 80) + colB;
                ldsm4(bvh[p], vd);
            }
#pragma unroll
            for (int ni2 = 0; ni2 < 8; ni2++) {
                int p = ni2 >> 1, o = ni2 & 1;
                uint32_t bq[2] = { bvh[p][o], bvh[p][o + 2] };
                mma_f16(oacc[ni2], aPh[c2], bq);
            }
        }
    }

    float inv0 = 1.0f / l0, inv1 = 1.0f / l1;
    int row0 = b * 1024 + brow + wm + g;
    int row1 = row0 + 8;
#pragma unroll
    for (int ni2 = 0; ni2 < 8; ni2++) {
        int cn = h * 64 + ni2 * 8 + 2 * t;
        *(float2*)&out[(size_t)row0 * 1024 + cn] =
            make_float2(oacc[ni2][0] * inv0, oacc[ni2][1] * inv0);
        *(float2*)&out[(size_t)row1 * 1024 + cn] =
            make_float2(oacc[ni2][2] * inv1, oacc[ni2][3] * inv1);
    }
}

// ---------------------------------------------------------------------------
extern "C" void kernel_launch(void* const* d_in, const int* in_sizes, int n_in,
                              void* d_out, int out_size) {
    (void)in_sizes; (void)n_in; (void)out_size;
    const float* x    = (const float*)d_in[0];
    const float* Wqv  = (const float*)d_in[1];
    const float* rr   = (const float*)d_in[2];
    const float* rw   = (const float*)d_in[3];
    const int*   mask = (const int*)d_in[4];
    float* out = (float*)d_out;

    cudaFuncSetAttribute(k_qv_mma, cudaFuncAttributeMaxDynamicSharedMemorySize, QV_SMEM);
    cudaFuncSetAttribute(k_flash,  cudaFuncAttributeMaxDynamicSharedMemorySize, FA_SMEM);

    k_trig<<<1024, 32>>>();
    k_decomp<<<16384 + 512, 256>>>(x, Wqv);
    k_qv_mma<<<dim3(32, 32), 256, QV_SMEM>>>(rr);
    k_build_A<<<8192, 256>>>(rr, rw);
    k_flash<<<dim3(8, 64), 256, FA_SMEM>>>(mask, out);
}

// round 16
// speedup vs baseline: 1.4956x; 1.0109x over previous
#include <cuda_runtime.h>
#include <cuda_fp16.h>
#include <math_constants.h>
#include <math.h>
#include <cstdint>

// B=4, L=1024, D=1024, H=16, HD=64.
// S[q,k] = (q+rr)·x_k + (q+rw)·pos[k-q+L] == Â[q]·K̂[k], K=128 (angle addition).
// R16: build_A folded into flash prologue (g_Ath/g_Atl deleted; 4 launches).

// ---------------------------------------------------------------------------
// Device scratch
// ---------------------------------------------------------------------------
__device__ __align__(16) __half g_xh[4096 * 1024];
__device__ __align__(16) __half g_xl[4096 * 1024];
__device__ __align__(16) __half g_wh[2048 * 1024];      // Wqv^T hi [n][k]
__device__ __align__(16) __half g_wl[2048 * 1024];
__device__ __align__(16) __half g_uh[4096 * 1024];      // u = q + rr, fp16 hi
__device__ __align__(16) __half g_ul[4096 * 1024];      // u lo
__device__ __align__(16) __half g_vth[64 * 64 * 1024];  // V^T fp16 [bh*64+d][tok]
__device__ __align__(16) float g_trig[1024 * 64];       // fp32 [p][i]=sin, [p][32+i]=cos
__device__ __align__(16) __half g_tgh[1024 * 64];       // fp16 hi of trig
__device__ __align__(16) __half g_tgl[1024 * 64];       // fp16 lo of trig

// ---------------------------------------------------------------------------
// helpers
// ---------------------------------------------------------------------------
__device__ __forceinline__ uint32_t smem_u32(const void* p) {
    uint32_t a;
    asm("{ .reg .u64 t; cvta.to.shared.u64 t, %1; cvt.u32.u64 %0, t; }" : "=r"(a) : "l"(p));
    return a;
}
__device__ __forceinline__ void mma_f16(float* c, const uint32_t* a, const uint32_t* b) {
    asm volatile(
        "mma.sync.aligned.m16n8k16.row.col.f32.f16.f16.f32 "
        "{%0,%1,%2,%3}, {%4,%5,%6,%7}, {%8,%9}, {%0,%1,%2,%3};"
        : "+f"(c[0]), "+f"(c[1]), "+f"(c[2]), "+f"(c[3])
        : "r"(a[0]), "r"(a[1]), "r"(a[2]), "r"(a[3]), "r"(b[0]), "r"(b[1]));
}
__device__ __forceinline__ void ldsm4(uint32_t* r, uint32_t addr) {
    asm volatile("ldmatrix.sync.aligned.m8n8.x4.shared.b16 {%0,%1,%2,%3}, [%4];"
        : "=r"(r[0]), "=r"(r[1]), "=r"(r[2]), "=r"(r[3]) : "r"(addr));
}
__device__ __forceinline__ uint32_t packh2(float e0, float e1) {
    __half2 h = __floats2half2_rn(e0, e1);
    return *(uint32_t*)&h;
}
#define CP16(saddr, gptr) \
    asm volatile("cp.async.ca.shared.global [%0], [%1], 16;" \
        :: "r"(saddr), "l"(__cvta_generic_to_global(gptr)))
#define CP_COMMIT() asm volatile("cp.async.commit_group;")
#define CP_WAIT(n)  asm volatile("cp.async.wait_group %0;" :: "n"(n))

// ---------------------------------------------------------------------------
// K0: trig tables (fp32 + fp16 hi/lo).
// ---------------------------------------------------------------------------
__global__ void k_trig() {
    int p = blockIdx.x, i = threadIdx.x;
    double f = exp(-(double)i * (log(10000.0) / 31.0));
    double ang = (double)p * f;
    float s = (float)sin(ang), c = (float)cos(ang);
    g_trig[p * 64 + i] = s;
    g_trig[p * 64 + 32 + i] = c;
    __half sh = __float2half_rn(s), ch = __float2half_rn(c);
    g_tgh[p * 64 + i] = sh;
    g_tgh[p * 64 + 32 + i] = ch;
    g_tgl[p * 64 + i] = __float2half_rn(s - __half2float(sh));
    g_tgl[p * 64 + 32 + i] = __float2half_rn(c - __half2float(ch));
}

// ---------------------------------------------------------------------------
// K1 (fused): x decomposition (blocks < 16384, coalesced) and W^T via smem
// tile transpose (blocks >= 16384: 16 k-tiles x 32 n-tiles of 64x64).
// ---------------------------------------------------------------------------
__global__ __launch_bounds__(256) void k_decomp(const float* __restrict__ x,
                                                const float* __restrict__ W) {
    __shared__ float tile[64][65];
    int bid = blockIdx.x;
    if (bid < 16384) {
        int idx = bid * 256 + threadIdx.x;
        float f = x[idx];
        __half h = __float2half_rn(f);
        g_xh[idx] = h;
        g_xl[idx] = __float2half_rn(f - __half2float(h));
    } else {
        int wt = bid - 16384;                 // 0..511
        int k0 = (wt >> 5) * 64;              // 16 k-tiles
        int n0 = (wt & 31) * 64;              // 32 n-tiles
        int tid = threadIdx.x;
#pragma unroll
        for (int it = 0; it < 16; it++) {
            int idx = tid + it * 256;         // 0..4095
            int r = idx >> 6, c = idx & 63;   // r = k, c = n
            tile[r][c] = W[(size_t)(k0 + r) * 2048 + n0 + c];
        }
        __syncthreads();
#pragma unroll
        for (int it = 0; it < 16; it++) {
            int idx = tid + it * 256;
            int r = idx >> 6, c = idx & 63;   // r = n, c = k
            float f = tile[c][r];
            __half h = __float2half_rn(f);
            size_t o = (size_t)(n0 + r) * 1024 + k0 + c;
            g_wh[o] = h;
            g_wl[o] = __float2half_rn(f - __half2float(h));
        }
    }
}

// ---------------------------------------------------------------------------
// K2: qv = x @ Wqv. q-half 3-product, v-half 1-product (xh·Wh).
// Epilogue: q -> uh/ul fp16 split; v -> g_vth fp16 TRANSPOSED (direct).
// ---------------------------------------------------------------------------
#define STAGE_BYTES 30720
#define QV_SMEM (2 * STAGE_BYTES)

__device__ __forceinline__ void stage_load(
    uint32_t sb, const __half* Ah, const __half* Al,
    const __half* Bh, const __half* Bl,
    size_t aRow, size_t bRow, int lda, int k0, int tid, bool lo)
{
#pragma unroll
    for (int it = 0; it < 2; it++) {
        int idx = tid + it * 256;
        int r = idx >> 2, c = idx & 3;
        uint32_t so = r * 80 + c * 16;
        size_t go = (aRow + r) * (size_t)lda + k0 + c * 8;
        CP16(sb + so, Ah + go);
        if (lo) CP16(sb + 10240 + so, Al + go);
    }
    {
        int r = tid >> 2, c = tid & 3;
        uint32_t so = r * 80 + c * 16;
        size_t go = (bRow + r) * (size_t)lda + k0 + c * 8;
        CP16(sb + 20480 + so, Bh + go);
        if (lo) CP16(sb + 25600 + so, Bl + go);
    }
}
__device__ __forceinline__ void stage_mma(uint32_t sb, int wm, int wn, int lane,
                                          float acc[2][4][4], bool three)
{
    int rsel = lane & 15;
    uint32_t csel = ((lane >> 4) << 3);
#pragma unroll
    for (int kc = 0; kc < 32; kc += 16) {
        uint32_t colB = (kc + csel) * 2;
        uint32_t ah[2][4], al[2][4], bhf[2][4], blf[2][4];
#pragma unroll
        for (int mi = 0; mi < 2; mi++) {
            uint32_t ad = sb + (uint32_t)((wm + mi * 16 + rsel) * 80) + colB;
            ldsm4(ah[mi], ad);
            if (three) ldsm4(al[mi], ad + 10240);
        }
#pragma unroll
        for (int p = 0; p < 2; p++) {
            uint32_t bd = sb + 20480 + (uint32_t)((wn + p * 16 + rsel) * 80) + colB;
            ldsm4(bhf[p], bd);
            if (three) ldsm4(blf[p], bd + 5120);
        }
#pragma unroll
        for (int mi = 0; mi < 2; mi++)
#pragma unroll
            for (int ni = 0; ni < 4; ni++) {
                int p = ni >> 1, o = ni & 1;
                uint32_t bq[2] = { bhf[p][o], bhf[p][o + 2] };
                mma_f16(acc[mi][ni], ah[mi], bq);
                if (three) {
                    uint32_t bql[2] = { blf[p][o], blf[p][o + 2] };
                    mma_f16(acc[mi][ni], ah[mi], bql);
                    mma_f16(acc[mi][ni], al[mi], bq);
                }
            }
    }
}

__global__ __launch_bounds__(256, 2) void k_qv_mma(const float* __restrict__ rr) {
    extern __shared__ char dynsmem[];
    uint32_t sbase = smem_u32(dynsmem);
    int tid = threadIdx.x, wid = tid >> 5, lane = tid & 31;
    int wm = (wid >> 1) * 32, wn = (wid & 1) * 32;
    int g = lane >> 2, t = lane & 3;
    int brow = blockIdx.y * 128, bcol = blockIdx.x * 64;
    bool is_q = (bcol < 1024);

    float acc[2][4][4] = {};
    const int NS = 32;
    stage_load(sbase, g_xh, g_xl, g_wh, g_wl, brow, bcol, 1024, 0, tid, is_q);
    CP_COMMIT();
    for (int s = 0; s < NS; s++) {
        CP_WAIT(0);
        __syncthreads();
        if (s + 1 < NS) {
            stage_load(sbase + ((s + 1) & 1) * STAGE_BYTES, g_xh, g_xl, g_wh, g_wl,
                       brow, bcol, 1024, (s + 1) * 32, tid, is_q);
            CP_COMMIT();
        }
        stage_mma(sbase + (s & 1) * STAGE_BYTES, wm, wn, lane, acc, is_q);
    }

#pragma unroll
    for (int mi = 0; mi < 2; mi++)
#pragma unroll
        for (int ni = 0; ni < 4; ni++) {
            int row0 = brow + wm + mi * 16 + g;
            int cn = bcol + wn + ni * 8 + 2 * t;
            float2 v0 = make_float2(acc[mi][ni][0], acc[mi][ni][1]);
            float2 v1 = make_float2(acc[mi][ni][2], acc[mi][ni][3]);
            if (is_q) {
                float2 rb = *(const float2*)(rr + cn);
                v0.x += rb.x; v0.y += rb.y;
                v1.x += rb.x; v1.y += rb.y;
                __half2 h0 = __floats2half2_rn(v0.x, v0.y);
                __half2 l0 = __floats2half2_rn(v0.x - __half2float(h0.x),
                                               v0.y - __half2float(h0.y));
                __half2 h1 = __floats2half2_rn(v1.x, v1.y);
                __half2 l1 = __floats2half2_rn(v1.x - __half2float(h1.x),
                                               v1.y - __half2float(h1.y));
                *(__half2*)&g_uh[(size_t)row0 * 1024 + cn] = h0;
                *(__half2*)&g_ul[(size_t)row0 * 1024 + cn] = l0;
                *(__half2*)&g_uh[(size_t)(row0 + 8) * 1024 + cn] = h1;
                *(__half2*)&g_ul[(size_t)(row0 + 8) * 1024 + cn] = l1;
            } else {
                // direct transposed V^T write: g_vth[(bh*64+d)*1024 + tok]
                int vc = cn - 1024;             // global v col, 0..1023
                int h2 = vc >> 6, d = vc & 63;  // head, in-head dim (d, d+1)
                int b2 = row0 >> 10, tok = row0 & 1023;
                size_t base = ((size_t)((b2 << 4) + h2) * 64 + d) * 1024 + tok;
                g_vth[base]            = __float2half_rn(v0.x);
                g_vth[base + 1024]     = __float2half_rn(v0.y);   // d+1
                g_vth[base + 8]        = __float2half_rn(v1.x);   // tok+8
                g_vth[base + 1024 + 8] = __float2half_rn(v1.y);
            }
        }
}

// ---------------------------------------------------------------------------
// K5: flash attention. Prologue computes the Â trig half in-CTA (same math as
// the old build_A) and stores it to smem chunks 2-3; content chunks 0-1 via
// cp.async from g_uh/g_ul. Rest unchanged from R12-R15.
// ---------------------------------------------------------------------------
#define FA_ACH 10240
#define FA_ALO 40960
#define FA_KBASE 81920
#define FA_KCH 5120
#define FA_KLO 20480
#define FA_VOFF 40960
#define FA_STAGE 51200
#define FA_SMEM (FA_KBASE + 2 * FA_STAGE)   // 184320

__device__ __forceinline__ void fa_load_kv(uint32_t sb, int bh, int b, int h,
                                           int kb, int buf, int tid) {
    uint32_t st = sb + FA_KBASE + buf * FA_STAGE;
#pragma unroll
    for (int it = 0; it < 4; it++) {
        int idx = tid + it * 256;
        int r = idx >> 4, cc = idx & 15;
        uint32_t so = (cc >> 2) * FA_KCH + r * 80 + (cc & 3) * 16;
        if (cc < 8) {
            size_t go = (size_t)(b * 1024 + kb + r) * 1024 + h * 64
                      + (cc >> 2) * 32 + (cc & 3) * 8;
            CP16(st + so, g_xh + go);
            CP16(st + FA_KLO + so, g_xl + go);
        } else {
            size_t go = (size_t)(kb + r) * 64 + ((cc >> 2) - 2) * 32 + (cc & 3) * 8;
            CP16(st + so, g_tgh + go);
            CP16(st + FA_KLO + so, g_tgl + go);
        }
    }
    uint32_t stV = st + FA_VOFF;
#pragma unroll
    for (int it = 0; it < 2; it++) {
        int idx = tid + it * 256;
        int r = idx >> 3, cc = idx & 7;
        int c = cc >> 2, c4 = cc & 3;
        uint32_t so = c * FA_KCH + r * 80 + c4 * 16;
        size_t go = (size_t)(bh * 64 + r) * 1024 + kb + c * 32 + c4 * 8;
        CP16(stV + so, g_vth + go);
    }
}

__global__ __launch_bounds__(256, 1) void k_flash(const int* __restrict__ mask,
                                                  const float* __restrict__ rr,
                                                  const float* __restrict__ rw,
                                                  float* __restrict__ out) {
    extern __shared__ char dynsmem[];
    __shared__ int msk[1024];
    uint32_t sb = smem_u32(dynsmem);
    int bh = blockIdx.y, b = bh >> 4, h = bh & 15;
    int brow = blockIdx.x * 128;
    int tid = threadIdx.x, wid = tid >> 5, lane = tid & 31;
    int wm = wid * 16;
    int g = lane >> 2, t = lane & 3;
    int rsel = lane & 15;
    uint32_t csel = ((lane >> 4) << 3);

    // ---- Â content chunks 0-1 via cp.async ----
#pragma unroll
    for (int it = 0; it < 4; it++) {
        int idx = tid + it * 256;              // 0..1023 = 128 rows x 8 cc
        int r = idx >> 3, cc = idx & 7;
        uint32_t so = (cc >> 2) * FA_ACH + r * 80 + (cc & 3) * 16;
        size_t go = (size_t)(b * 1024 + brow + r) * 1024 + h * 64
                  + (cc >> 2) * 32 + (cc & 3) * 8;
        CP16(sb + so, g_uh + go);
        CP16(sb + FA_ALO + so, g_ul + go);
    }
    fa_load_kv(sb, bh, b, h, 0, 0, tid);
    CP_COMMIT();

    // ---- Â trig half computed in-CTA (identical math to old build_A) ----
    {
        int i = lane;                          // 0..31 = dim
        float rr0 = rr[h * 64 + i],      rw0 = rw[h * 64 + i];
        float rr1 = rr[h * 64 + 32 + i], rw1 = rw[h * 64 + 32 + i];
#pragma unroll
        for (int j = 0; j < 16; j++) {
            int r = wid * 16 + j;              // 0..127
            size_t uo = (size_t)(b * 1024 + brow + r) * 1024 + h * 64;
            float u0 = __half2float(g_uh[uo + i]) + __half2float(g_ul[uo + i]);
            float u1 = __half2float(g_uh[uo + 32 + i]) + __half2float(g_ul[uo + 32 + i]);
            float w0 = u0 - rr0 + rw0;
            float w1 = u1 - rr1 + rw1;
            const float* tg = g_trig + (size_t)(brow + r) * 64;
            float sq = tg[i], cq = tg[32 + i];
            float a1 = w0 * cq + w1 * sq;
            float a2 = w1 * cq - w0 * sq;
            __half hh1 = __float2half_rn(a1);
            __half hh2 = __float2half_rn(a2);
            uint32_t off = (uint32_t)(r * 80 + i * 2);
            *(__half*)(dynsmem + 2 * FA_ACH + off) = hh1;
            *(__half*)(dynsmem + FA_ALO + 2 * FA_ACH + off) =
                __float2half_rn(a1 - __half2float(hh1));
            *(__half*)(dynsmem + 3 * FA_ACH + off) = hh2;
            *(__half*)(dynsmem + FA_ALO + 3 * FA_ACH + off) =
                __float2half_rn(a2 - __half2float(hh2));
        }
    }
    for (int i = tid; i < 1024; i += 256) msk[i] = mask[b * 1024 + i];

    float oacc[8][4] = {};
    float m0 = -CUDART_INF_F, m1 = -CUDART_INF_F, l0 = 0.0f, l1 = 0.0f;

    const int NT = 16;
    for (int kt = 0; kt < NT; kt++) {
        CP_WAIT(0);
        __syncthreads();
        if (kt + 1 < NT) {
            fa_load_kv(sb, bh, b, h, (kt + 1) * 64, (kt + 1) & 1, tid);
            CP_COMMIT();
        }

        uint32_t Ks = sb + FA_KBASE + (kt & 1) * FA_STAGE;
        float sacc[8][4] = {};
#pragma unroll
        for (int ks = 0; ks < 8; ks++) {
            int c = ks >> 1;
            uint32_t colB = (((ks & 1) * 16) + csel) * 2;
            uint32_t ah[4], al[4], bhf[4][4], blf[4][4];
            uint32_t ad = sb + (uint32_t)(c * FA_ACH) + (uint32_t)((wm + rsel) * 80) + colB;
            ldsm4(ah, ad);
            ldsm4(al, ad + FA_ALO);
#pragma unroll
            for (int p = 0; p < 4; p++) {
                uint32_t kd = Ks + (uint32_t)(c * FA_KCH) + (uint32_t)((p * 16 + rsel) * 80) + colB;
                ldsm4(bhf[p], kd);
                ldsm4(blf[p], kd + FA_KLO);
            }
#pragma unroll
            for (int ni = 0; ni < 8; ni++) {
                int p = ni >> 1, o = ni & 1;
                uint32_t bq[2]  = { bhf[p][o], bhf[p][o + 2] };
                uint32_t bql[2] = { blf[p][o], blf[p][o + 2] };
                mma_f16(sacc[ni], ah, bq);
                mma_f16(sacc[ni], ah, bql);
                mma_f16(sacc[ni], al, bq);
            }
        }

        int kb = kt * 64;
        float tmax0 = -CUDART_INF_F, tmax1 = -CUDART_INF_F;
#pragma unroll
        for (int ni = 0; ni < 8; ni++) {
            int kc = kb + ni * 8 + 2 * t;
            if (msk[kc] == 0)     { sacc[ni][0] = -CUDART_INF_F; sacc[ni][2] = -CUDART_INF_F; }
            if (msk[kc + 1] == 0) { sacc[ni][1] = -CUDART_INF_F; sacc[ni][3] = -CUDART_INF_F; }
            tmax0 = fmaxf(tmax0, fmaxf(sacc[ni][0], sacc[ni][1]));
            tmax1 = fmaxf(tmax1, fmaxf(sacc[ni][2], sacc[ni][3]));
        }
        tmax0 = fmaxf(tmax0, __shfl_xor_sync(0xffffffffu, tmax0, 1));
        tmax0 = fmaxf(tmax0, __shfl_xor_sync(0xffffffffu, tmax0, 2));
        tmax1 = fmaxf(tmax1, __shfl_xor_sync(0xffffffffu, tmax1, 1));
        tmax1 = fmaxf(tmax1, __shfl_xor_sync(0xffffffffu, tmax1, 2));
        float nm0 = fmaxf(m0, tmax0), nm1 = fmaxf(m1, tmax1);
        float sc0 = __expf(m0 - nm0), sc1 = __expf(m1 - nm1);
        m0 = nm0; m1 = nm1;

        float rs0 = 0.0f, rs1 = 0.0f;
        uint32_t aPh[4][4];
#pragma unroll
        for (int ni = 0; ni < 8; ni++) {
            float p0 = __expf(sacc[ni][0] - nm0);
            float p1 = __expf(sacc[ni][1] - nm0);
            float p2 = __expf(sacc[ni][2] - nm1);
            float p3 = __expf(sacc[ni][3] - nm1);
            rs0 += p0 + p1;
            rs1 += p2 + p3;
            int c2 = ni >> 1, o = ni & 1;
            aPh[c2][o * 2 + 0] = packh2(p0, p1);
            aPh[c2][o * 2 + 1] = packh2(p2, p3);
        }
        rs0 += __shfl_xor_sync(0xffffffffu, rs0, 1);
        rs0 += __shfl_xor_sync(0xffffffffu, rs0, 2);
        rs1 += __shfl_xor_sync(0xffffffffu, rs1, 1);
        rs1 += __shfl_xor_sync(0xffffffffu, rs1, 2);
        l0 = l0 * sc0 + rs0;
        l1 = l1 * sc1 + rs1;
#pragma unroll
        for (int ni2 = 0; ni2 < 8; ni2++) {
            oacc[ni2][0] *= sc0; oacc[ni2][1] *= sc0;
            oacc[ni2][2] *= sc1; oacc[ni2][3] *= sc1;
        }

        uint32_t Vs = Ks + FA_VOFF;
#pragma unroll
        for (int c2 = 0; c2 < 4; c2++) {
            int c = c2 >> 1;
            uint32_t colB = (((c2 & 1) * 16) + csel) * 2;
            uint32_t bvh[4][4];
#pragma unroll
            for (int p = 0; p < 4; p++) {
                uint32_t vd = Vs + (uint32_t)(c * FA_KCH) + (uint32_t)((p * 16 + rsel) * 80) + colB;
                ldsm4(bvh[p], vd);
            }
#pragma unroll
            for (int ni2 = 0; ni2 < 8; ni2++) {
                int p = ni2 >> 1, o = ni2 & 1;
                uint32_t bq[2] = { bvh[p][o], bvh[p][o + 2] };
                mma_f16(oacc[ni2], aPh[c2], bq);
            }
        }
    }

    float inv0 = 1.0f / l0, inv1 = 1.0f / l1;
    int row0 = b * 1024 + brow + wm + g;
    int row1 = row0 + 8;
#pragma unroll
    for (int ni2 = 0; ni2 < 8; ni2++) {
        int cn = h * 64 + ni2 * 8 + 2 * t;
        *(float2*)&out[(size_t)row0 * 1024 + cn] =
            make_float2(oacc[ni2][0] * inv0, oacc[ni2][1] * inv0);
        *(float2*)&out[(size_t)row1 * 1024 + cn] =
            make_float2(oacc[ni2][2] * inv1, oacc[ni2][3] * inv1);
    }
}

// ---------------------------------------------------------------------------
extern "C" void kernel_launch(void* const* d_in, const int* in_sizes, int n_in,
                              void* d_out, int out_size) {
    (void)in_sizes; (void)n_in; (void)out_size;
    const float* x    = (const float*)d_in[0];
    const float* Wqv  = (const float*)d_in[1];
    const float* rr   = (const float*)d_in[2];
    const float* rw   = (const float*)d_in[3];
    const int*   mask = (const int*)d_in[4];
    float* out = (float*)d_out;

    cudaFuncSetAttribute(k_qv_mma, cudaFuncAttributeMaxDynamicSharedMemorySize, QV_SMEM);
    cudaFuncSetAttribute(k_flash,  cudaFuncAttributeMaxDynamicSharedMemorySize, FA_SMEM);

    k_trig<<<1024, 32>>>();
    k_decomp<<<16384 + 512, 256>>>(x, Wqv);
    k_qv_mma<<<dim3(32, 32), 256, QV_SMEM>>>(rr);
    k_flash<<<dim3(8, 64), 256, FA_SMEM>>>(mask, rr, rw, out);
}